// round 1
// baseline (speedup 1.0000x reference)
#include <cuda_runtime.h>
#include <cuda_bf16.h>
#include <math.h>

// ---------------- problem constants ----------------
#define MAXN 50000
#define MAXE 800000
#define MAXTOT (MAXE + MAXN)

// ---------------- device scratch (no allocations allowed) ----------------
__device__ float g_xw[MAXN * 256];   // xw of current layer (F = 256 or 128)
__device__ float g_h[MAXN * 256];    // layer-1 output (input to layer 2)
__device__ float g_asrc[MAXN];
__device__ float g_adst[MAXN];
__device__ float g_m[MAXN];
__device__ float g_dsum[MAXN];
__device__ int   g_cnt[MAXN];        // counts, then cursors
__device__ int   g_off[MAXN + 1];    // CSR offsets (by dst)
__device__ int   g_csrc[MAXTOT];     // CSR source node per incoming edge
__device__ int   g_is64;             // edge_index dtype flag

// ---------------- dtype detection ----------------
__global__ void detect_kernel(const int* __restrict__ ei) {
    if (threadIdx.x == 0 && blockIdx.x == 0) {
        int z = 1;
        #pragma unroll
        for (int i = 1; i < 64; i += 2)
            if (ei[i] != 0) z = 0;
        g_is64 = z;
    }
}

__device__ __forceinline__ int load_idx(const int* __restrict__ ei, long long elem, int is64) {
    return is64 ? ei[2 * elem] : ei[elem];
}

// ---------------- CSR build ----------------
__global__ void init_cnt_kernel(int n) {
    int i = blockIdx.x * blockDim.x + threadIdx.x;
    if (i < n) g_cnt[i] = 1;  // self loop
}

__global__ void hist_kernel(const int* __restrict__ ei, int E) {
    int i = blockIdx.x * blockDim.x + threadIdx.x;
    if (i >= E) return;
    int is64 = g_is64;
    int d = load_idx(ei, (long long)E + i, is64);
    atomicAdd(&g_cnt[d], 1);
}

// single-block exclusive scan over g_cnt[0..n) -> g_off
__global__ void scan_kernel(int n) {
    __shared__ int sh[1024];
    __shared__ int carry;
    if (threadIdx.x == 0) carry = 0;
    __syncthreads();
    for (int base = 0; base < n; base += 1024) {
        int i = base + threadIdx.x;
        int v = (i < n) ? g_cnt[i] : 0;
        sh[threadIdx.x] = v;
        __syncthreads();
        // Hillis-Steele inclusive scan
        for (int ofs = 1; ofs < 1024; ofs <<= 1) {
            int t = (threadIdx.x >= ofs) ? sh[threadIdx.x - ofs] : 0;
            __syncthreads();
            sh[threadIdx.x] += t;
            __syncthreads();
        }
        if (i < n) g_off[i] = carry + sh[threadIdx.x] - v;  // exclusive
        __syncthreads();
        if (threadIdx.x == 1023) carry += sh[1023];
        __syncthreads();
    }
    if (threadIdx.x == 0) g_off[n] = carry;
}

__global__ void selfloop_kernel(int n) {
    int i = blockIdx.x * blockDim.x + threadIdx.x;
    if (i >= n) return;
    int p = g_off[i];
    g_csrc[p] = i;       // self loop first
    g_cnt[i] = p + 1;    // cursor
}

__global__ void scatter_kernel(const int* __restrict__ ei, int E) {
    int i = blockIdx.x * blockDim.x + threadIdx.x;
    if (i >= E) return;
    int is64 = g_is64;
    int s = load_idx(ei, i, is64);
    int d = load_idx(ei, (long long)E + i, is64);
    int p = atomicAdd(&g_cnt[d], 1);
    g_csrc[p] = s;
}

// ---------------- GEMM: C[M,N] = A[M,K] @ B[K,N], fp32 ----------------
#define BM 128
#define BN 128
#define BKK 8

__global__ __launch_bounds__(256) void gemm_kernel(
    const float* __restrict__ A, const float* __restrict__ B,
    float* __restrict__ C, int M, int K, int N)
{
    __shared__ float As[BKK][BM];
    __shared__ float Bs[BKK][BN];
    int tid = threadIdx.x;
    int r0 = blockIdx.x * BM;
    int c0 = blockIdx.y * BN;
    int ty = tid / 16, tx = tid % 16;

    float acc[8][8];
    #pragma unroll
    for (int i = 0; i < 8; i++)
        #pragma unroll
        for (int j = 0; j < 8; j++) acc[i][j] = 0.f;

    int a_row = tid >> 1;           // 0..127
    int a_c4  = (tid & 1) * 4;      // 0 or 4
    int b_row = tid >> 5;           // 0..7
    int b_c4  = (tid & 31) * 4;     // 0..124

    for (int k0 = 0; k0 < K; k0 += BKK) {
        float4 av = make_float4(0.f, 0.f, 0.f, 0.f);
        int gr = r0 + a_row;
        if (gr < M) av = *(const float4*)(A + (size_t)gr * K + k0 + a_c4);
        As[a_c4 + 0][a_row] = av.x;
        As[a_c4 + 1][a_row] = av.y;
        As[a_c4 + 2][a_row] = av.z;
        As[a_c4 + 3][a_row] = av.w;
        float4 bv = *(const float4*)(B + (size_t)(k0 + b_row) * N + c0 + b_c4);
        *(float4*)(&Bs[b_row][b_c4]) = bv;
        __syncthreads();
        #pragma unroll
        for (int kk = 0; kk < BKK; kk++) {
            float ra[8], rb[8];
            *(float4*)(ra)     = *(const float4*)(&As[kk][ty * 8]);
            *(float4*)(ra + 4) = *(const float4*)(&As[kk][ty * 8 + 4]);
            *(float4*)(rb)     = *(const float4*)(&Bs[kk][tx * 8]);
            *(float4*)(rb + 4) = *(const float4*)(&Bs[kk][tx * 8 + 4]);
            #pragma unroll
            for (int i = 0; i < 8; i++)
                #pragma unroll
                for (int j = 0; j < 8; j++)
                    acc[i][j] += ra[i] * rb[j];
        }
        __syncthreads();
    }
    #pragma unroll
    for (int i = 0; i < 8; i++) {
        int gr = r0 + ty * 8 + i;
        if (gr < M) {
            float4 v0 = make_float4(acc[i][0], acc[i][1], acc[i][2], acc[i][3]);
            float4 v1 = make_float4(acc[i][4], acc[i][5], acc[i][6], acc[i][7]);
            *(float4*)(C + (size_t)gr * N + c0 + tx * 8)     = v0;
            *(float4*)(C + (size_t)gr * N + c0 + tx * 8 + 4) = v1;
        }
    }
}

// ---------------- alpha = xw @ a_src, xw @ a_dst (warp per row) ----------------
template<int F>
__global__ void alpha_kernel(const float* __restrict__ xw,
                             const float* __restrict__ avs,
                             const float* __restrict__ avd, int n)
{
    int w = (blockIdx.x * blockDim.x + threadIdx.x) >> 5;
    int lane = threadIdx.x & 31;
    if (w >= n) return;
    const float4* row = (const float4*)(xw + (size_t)w * F);
    const float4* as4 = (const float4*)avs;
    const float4* ad4 = (const float4*)avd;
    float ss = 0.f, sd = 0.f;
    #pragma unroll
    for (int k = 0; k < F / 128; k++) {
        float4 v = row[lane + 32 * k];
        float4 a = as4[lane + 32 * k];
        float4 b = ad4[lane + 32 * k];
        ss += v.x * a.x + v.y * a.y + v.z * a.z + v.w * a.w;
        sd += v.x * b.x + v.y * b.y + v.z * b.z + v.w * b.w;
    }
    #pragma unroll
    for (int o = 16; o; o >>= 1) {
        ss += __shfl_xor_sync(~0u, ss, o);
        sd += __shfl_xor_sync(~0u, sd, o);
    }
    if (lane == 0) { g_asrc[w] = ss; g_adst[w] = sd; }
}

// ---------------- segment softmax stats (warp per node, online) ----------------
__global__ void stats_kernel(int n) {
    int w = (blockIdx.x * blockDim.x + threadIdx.x) >> 5;
    int lane = threadIdx.x & 31;
    if (w >= n) return;
    int beg = g_off[w], end = g_off[w + 1];
    float adi = g_adst[w];
    float mx = -1e30f, sm = 0.f;
    for (int k = beg + lane; k < end; k += 32) {
        int s = g_csrc[k];
        float e = g_asrc[s] + adi;
        e = e >= 0.f ? e : 0.2f * e;
        if (e > mx) { sm = sm * __expf(mx - e) + 1.f; mx = e; }
        else        { sm += __expf(e - mx); }
    }
    #pragma unroll
    for (int o = 16; o; o >>= 1) {
        float mo = __shfl_xor_sync(~0u, mx, o);
        float so = __shfl_xor_sync(~0u, sm, o);
        float nm = fmaxf(mx, mo);
        sm = sm * __expf(mx - nm) + so * __expf(mo - nm);
        mx = nm;
    }
    if (lane == 0) { g_m[w] = mx; g_dsum[w] = sm; }
}

// ---------------- aggregation (warp per node, gather) ----------------
template<int F, bool RELU>
__global__ void agg_kernel(const float* __restrict__ xw,
                           const float* __restrict__ bias,
                           float* __restrict__ out, int n)
{
    int w = (blockIdx.x * blockDim.x + threadIdx.x) >> 5;
    int lane = threadIdx.x & 31;
    if (w >= n) return;
    int beg = g_off[w], end = g_off[w + 1];
    float adi = g_adst[w];
    float mi  = g_m[w];
    float inv = 1.f / g_dsum[w];
    float4 acc0 = make_float4(0.f, 0.f, 0.f, 0.f);
    float4 acc1 = make_float4(0.f, 0.f, 0.f, 0.f);
    for (int k = beg; k < end; k++) {
        int s = g_csrc[k];
        float e = g_asrc[s] + adi;
        e = e >= 0.f ? e : 0.2f * e;
        float att = __expf(e - mi) * inv;
        const float4* row = (const float4*)(xw + (size_t)s * F);
        float4 v = row[lane];
        acc0.x += att * v.x; acc0.y += att * v.y;
        acc0.z += att * v.z; acc0.w += att * v.w;
        if (F == 256) {
            float4 v1 = row[32 + lane];
            acc1.x += att * v1.x; acc1.y += att * v1.y;
            acc1.z += att * v1.z; acc1.w += att * v1.w;
        }
    }
    const float4* b4 = (const float4*)bias;
    float4 b0 = b4[lane];
    acc0.x += b0.x; acc0.y += b0.y; acc0.z += b0.z; acc0.w += b0.w;
    if (RELU) {
        acc0.x = fmaxf(acc0.x, 0.f); acc0.y = fmaxf(acc0.y, 0.f);
        acc0.z = fmaxf(acc0.z, 0.f); acc0.w = fmaxf(acc0.w, 0.f);
    }
    float4* o4 = (float4*)(out + (size_t)w * F);
    o4[lane] = acc0;
    if (F == 256) {
        float4 b1v = b4[32 + lane];
        acc1.x += b1v.x; acc1.y += b1v.y; acc1.z += b1v.z; acc1.w += b1v.w;
        if (RELU) {
            acc1.x = fmaxf(acc1.x, 0.f); acc1.y = fmaxf(acc1.y, 0.f);
            acc1.z = fmaxf(acc1.z, 0.f); acc1.w = fmaxf(acc1.w, 0.f);
        }
        o4[32 + lane] = acc1;
    }
}

// ---------------- launch ----------------
extern "C" void kernel_launch(void* const* d_in, const int* in_sizes, int n_in,
                              void* d_out, int out_size) {
    const float* x   = (const float*)d_in[0];
    const int*   ei  = (const int*)d_in[1];   // int32 view (handles int64 via g_is64)
    const float* W1  = (const float*)d_in[2];
    const float* a1s = (const float*)d_in[3];
    const float* a1d = (const float*)d_in[4];
    const float* b1  = (const float*)d_in[5];
    const float* W2  = (const float*)d_in[6];
    const float* a2s = (const float*)d_in[7];
    const float* a2d = (const float*)d_in[8];
    const float* b2  = (const float*)d_in[9];
    float* out = (float*)d_out;

    int n = in_sizes[0] / 128;        // 50000
    int E = in_sizes[1] / 2;          // 800000

    float *p_xw = nullptr, *p_h = nullptr;
    cudaGetSymbolAddress((void**)&p_xw, g_xw);
    cudaGetSymbolAddress((void**)&p_h,  g_h);

    int nblk      = (n + 255) / 256;
    int eblk      = (E + 255) / 256;
    int warpBlk   = (n * 32 + 255) / 256;
    dim3 g1((n + BM - 1) / BM, 256 / BN);   // GEMM1: N=256
    dim3 g2((n + BM - 1) / BM, 128 / BN);   // GEMM2: N=128

    // dtype sniff + CSR build (shared by both layers)
    detect_kernel<<<1, 32>>>(ei);
    init_cnt_kernel<<<nblk, 256>>>(n);
    hist_kernel<<<eblk, 256>>>(ei, E);
    scan_kernel<<<1, 1024>>>(n);
    selfloop_kernel<<<nblk, 256>>>(n);
    scatter_kernel<<<eblk, 256>>>(ei, E);

    // ---- layer 1: Fin=128 -> H=256, relu ----
    gemm_kernel<<<g1, 256>>>(x, W1, p_xw, n, 128, 256);
    alpha_kernel<256><<<warpBlk, 256>>>(p_xw, a1s, a1d, n);
    stats_kernel<<<warpBlk, 256>>>(n);
    agg_kernel<256, true><<<warpBlk, 256>>>(p_xw, b1, p_h, n);

    // ---- layer 2: H=256 -> Fout=128, no relu ----
    gemm_kernel<<<g2, 256>>>(p_h, W2, p_xw, n, 256, 128);
    alpha_kernel<128><<<warpBlk, 256>>>(p_xw, a2s, a2d, n);
    stats_kernel<<<warpBlk, 256>>>(n);
    agg_kernel<128, false><<<warpBlk, 256>>>(p_xw, b2, out, n);
}

// round 2
// speedup vs baseline: 1.2854x; 1.2854x over previous
#include <cuda_runtime.h>
#include <cuda_bf16.h>
#include <mma.h>
#include <math.h>

using namespace nvcuda;

// ---------------- problem constants ----------------
#define MAXN 50000
#define NPAD 50048              // padded rows so wmma stores never go OOB (scratch only)
#define MAXE 800000
#define MAXTOT (MAXE + MAXN)

// ---------------- device scratch (no allocations allowed) ----------------
__device__ float g_xw[(size_t)NPAD * 256];   // xw of current layer (fp32)
__device__ float g_h[(size_t)MAXN * 256];    // layer-1 output
__device__ __nv_bfloat16 g_ah[(size_t)MAXN * 256];  // A hi (bf16)
__device__ __nv_bfloat16 g_al[(size_t)MAXN * 256];  // A lo (bf16)
__device__ __nv_bfloat16 g_bhw[65536];       // B hi
__device__ __nv_bfloat16 g_blw[65536];       // B lo
__device__ float g_asrc[MAXN];
__device__ float g_adst[MAXN];
__device__ float g_m[MAXN];
__device__ float g_dsum[MAXN];
__device__ int   g_cnt[MAXN];
__device__ int   g_off[MAXN + 1];
__device__ int   g_csrc[MAXTOT];
__device__ int   g_bsum[64];
__device__ int   g_total;
__device__ int   g_is64;

// ---------------- dtype detection ----------------
__global__ void detect_kernel(const int* __restrict__ ei) {
    if (threadIdx.x == 0 && blockIdx.x == 0) {
        int z = 1;
        #pragma unroll
        for (int i = 1; i < 64; i += 2)
            if (ei[i] != 0) z = 0;
        g_is64 = z;
    }
}

__device__ __forceinline__ int load_idx(const int* __restrict__ ei, long long elem, int is64) {
    return is64 ? ei[2 * elem] : ei[elem];
}

// ---------------- CSR build ----------------
__global__ void init_cnt_kernel(int n) {
    int i = blockIdx.x * blockDim.x + threadIdx.x;
    if (i < n) g_cnt[i] = 1;  // self loop
}

__global__ void hist_kernel(const int* __restrict__ ei, int E) {
    int i = blockIdx.x * blockDim.x + threadIdx.x;
    if (i >= E) return;
    int d = load_idx(ei, (long long)E + i, g_is64);
    atomicAdd(&g_cnt[d], 1);
}

// multi-block scan: phase 1 — per-block exclusive scan + block sums
__global__ __launch_bounds__(1024) void blockscan_kernel(int n) {
    __shared__ int warpsum[32];
    int i = blockIdx.x * 1024 + threadIdx.x;
    int v = (i < n) ? g_cnt[i] : 0;
    int lane = threadIdx.x & 31, wid = threadIdx.x >> 5;
    int s = v;
    #pragma unroll
    for (int o = 1; o < 32; o <<= 1) {
        int t = __shfl_up_sync(~0u, s, o);
        if (lane >= o) s += t;
    }
    if (lane == 31) warpsum[wid] = s;
    __syncthreads();
    if (wid == 0) {
        int ws = warpsum[lane];
        #pragma unroll
        for (int o = 1; o < 32; o <<= 1) {
            int t = __shfl_up_sync(~0u, ws, o);
            if (lane >= o) ws += t;
        }
        warpsum[lane] = ws;
    }
    __syncthreads();
    int excl = s - v + (wid ? warpsum[wid - 1] : 0);
    if (i < n) g_off[i] = excl;
    if (threadIdx.x == 1023) g_bsum[blockIdx.x] = excl + v;
}

// phase 2 — serial scan of <=64 block sums (trivial)
__global__ void scanb_kernel(int nb) {
    if (threadIdx.x == 0 && blockIdx.x == 0) {
        int run = 0;
        for (int b = 0; b < nb; b++) { int t = g_bsum[b]; g_bsum[b] = run; run += t; }
        g_total = run;
    }
}

// phase 3 — add block offsets
__global__ void addoff_kernel(int n) {
    int i = blockIdx.x * 1024 + threadIdx.x;
    if (i < n) g_off[i] += g_bsum[i >> 10];
    if (i == 0) g_off[n] = g_total;
}

__global__ void selfloop_kernel(int n) {
    int i = blockIdx.x * blockDim.x + threadIdx.x;
    if (i >= n) return;
    int p = g_off[i];
    g_csrc[p] = i;
    g_cnt[i] = p + 1;
}

__global__ void scatter_kernel(const int* __restrict__ ei, int E) {
    int i = blockIdx.x * blockDim.x + threadIdx.x;
    if (i >= E) return;
    int is64 = g_is64;
    int s = load_idx(ei, i, is64);
    int d = load_idx(ei, (long long)E + i, is64);
    int p = atomicAdd(&g_cnt[d], 1);
    g_csrc[p] = s;
}

// ---------------- fp32 -> bf16 hi/lo split ----------------
__global__ void split_kernel(const float* __restrict__ src,
                             __nv_bfloat16* __restrict__ hi,
                             __nv_bfloat16* __restrict__ lo, int n4) {
    int i = blockIdx.x * blockDim.x + threadIdx.x;
    if (i >= n4) return;
    float4 v = ((const float4*)src)[i];
    __nv_bfloat16 h0 = __float2bfloat16(v.x);
    __nv_bfloat16 h1 = __float2bfloat16(v.y);
    __nv_bfloat16 h2 = __float2bfloat16(v.z);
    __nv_bfloat16 h3 = __float2bfloat16(v.w);
    __nv_bfloat16 l0 = __float2bfloat16(v.x - __bfloat162float(h0));
    __nv_bfloat16 l1 = __float2bfloat16(v.y - __bfloat162float(h1));
    __nv_bfloat16 l2 = __float2bfloat16(v.z - __bfloat162float(h2));
    __nv_bfloat16 l3 = __float2bfloat16(v.w - __bfloat162float(h3));
    __nv_bfloat162* h2p = (__nv_bfloat162*)hi;
    __nv_bfloat162* l2p = (__nv_bfloat162*)lo;
    h2p[2 * i]     = __nv_bfloat162(h0, h1);
    h2p[2 * i + 1] = __nv_bfloat162(h2, h3);
    l2p[2 * i]     = __nv_bfloat162(l0, l1);
    l2p[2 * i + 1] = __nv_bfloat162(l2, l3);
}

// ---------------- GEMM via bf16 wmma, hi/lo compensated ----------------
#define GBM 128
#define GBN 64
#define LDA 24
#define LDB 72

__global__ __launch_bounds__(256) void gemm_wmma_kernel(
    const __nv_bfloat16* __restrict__ Ah, const __nv_bfloat16* __restrict__ Al,
    const __nv_bfloat16* __restrict__ Bh, const __nv_bfloat16* __restrict__ Bl,
    float* __restrict__ C, int M, int K, int N)
{
    __shared__ __nv_bfloat16 sAh[GBM][LDA], sAl[GBM][LDA];
    __shared__ __nv_bfloat16 sBh[16][LDB],  sBl[16][LDB];
    int r0 = blockIdx.x * GBM, c0 = blockIdx.y * GBN;
    int wid = threadIdx.x >> 5;
    int tid = threadIdx.x;

    wmma::fragment<wmma::accumulator, 16, 16, 16, float> acc[4];
    #pragma unroll
    for (int j = 0; j < 4; j++) wmma::fill_fragment(acc[j], 0.f);

    for (int k0 = 0; k0 < K; k0 += 16) {
        {   // A tile: 128 x 16 (hi & lo); 16B per thread per matrix
            int row = tid >> 1, hc = (tid & 1) * 8;
            int gr = r0 + row;
            uint4 vh = make_uint4(0, 0, 0, 0), vl = make_uint4(0, 0, 0, 0);
            if (gr < M) {
                vh = *(const uint4*)(Ah + (size_t)gr * K + k0 + hc);
                vl = *(const uint4*)(Al + (size_t)gr * K + k0 + hc);
            }
            *(uint4*)&sAh[row][hc] = vh;
            *(uint4*)&sAl[row][hc] = vl;
        }
        {   // B tile: 16 x 64 (hi & lo); 8B per thread per matrix
            int row = tid >> 4, hc = (tid & 15) * 4;
            uint2 vh = *(const uint2*)(Bh + (size_t)(k0 + row) * N + c0 + hc);
            uint2 vl = *(const uint2*)(Bl + (size_t)(k0 + row) * N + c0 + hc);
            *(uint2*)&sBh[row][hc] = vh;
            *(uint2*)&sBl[row][hc] = vl;
        }
        __syncthreads();
        wmma::fragment<wmma::matrix_a, 16, 16, 16, __nv_bfloat16, wmma::row_major> fah, fal;
        wmma::load_matrix_sync(fah, &sAh[wid * 16][0], LDA);
        wmma::load_matrix_sync(fal, &sAl[wid * 16][0], LDA);
        #pragma unroll
        for (int j = 0; j < 4; j++) {
            wmma::fragment<wmma::matrix_b, 16, 16, 16, __nv_bfloat16, wmma::row_major> fbh, fbl;
            wmma::load_matrix_sync(fbh, &sBh[0][j * 16], LDB);
            wmma::load_matrix_sync(fbl, &sBl[0][j * 16], LDB);
            wmma::mma_sync(acc[j], fah, fbh, acc[j]);
            wmma::mma_sync(acc[j], fah, fbl, acc[j]);
            wmma::mma_sync(acc[j], fal, fbh, acc[j]);
        }
        __syncthreads();
    }
    int gr = r0 + wid * 16;   // C is padded scratch (NPAD rows) — no OOB
    #pragma unroll
    for (int j = 0; j < 4; j++)
        wmma::store_matrix_sync(C + (size_t)gr * N + c0 + j * 16, acc[j], N, wmma::mem_row_major);
}

// ---------------- alpha = xw @ a_src, xw @ a_dst (warp per row) ----------------
template<int F>
__global__ void alpha_kernel(const float* __restrict__ xw,
                             const float* __restrict__ avs,
                             const float* __restrict__ avd, int n)
{
    int w = (blockIdx.x * blockDim.x + threadIdx.x) >> 5;
    int lane = threadIdx.x & 31;
    if (w >= n) return;
    const float4* row = (const float4*)(xw + (size_t)w * F);
    const float4* as4 = (const float4*)avs;
    const float4* ad4 = (const float4*)avd;
    float ss = 0.f, sd = 0.f;
    #pragma unroll
    for (int k = 0; k < F / 128; k++) {
        float4 v = row[lane + 32 * k];
        float4 a = as4[lane + 32 * k];
        float4 b = ad4[lane + 32 * k];
        ss += v.x * a.x + v.y * a.y + v.z * a.z + v.w * a.w;
        sd += v.x * b.x + v.y * b.y + v.z * b.z + v.w * b.w;
    }
    #pragma unroll
    for (int o = 16; o; o >>= 1) {
        ss += __shfl_xor_sync(~0u, ss, o);
        sd += __shfl_xor_sync(~0u, sd, o);
    }
    if (lane == 0) { g_asrc[w] = ss; g_adst[w] = sd; }
}

// ---------------- segment softmax stats (warp per node, online) ----------------
__global__ void stats_kernel(int n) {
    int w = (blockIdx.x * blockDim.x + threadIdx.x) >> 5;
    int lane = threadIdx.x & 31;
    if (w >= n) return;
    int beg = g_off[w], end = g_off[w + 1];
    float adi = g_adst[w];
    float mx = -1e30f, sm = 0.f;
    for (int k = beg + lane; k < end; k += 32) {
        int s = g_csrc[k];
        float e = g_asrc[s] + adi;
        e = e >= 0.f ? e : 0.2f * e;
        if (e > mx) { sm = sm * __expf(mx - e) + 1.f; mx = e; }
        else        { sm += __expf(e - mx); }
    }
    #pragma unroll
    for (int o = 16; o; o >>= 1) {
        float mo = __shfl_xor_sync(~0u, mx, o);
        float so = __shfl_xor_sync(~0u, sm, o);
        float nm = fmaxf(mx, mo);
        sm = sm * __expf(mx - nm) + so * __expf(mo - nm);
        mx = nm;
    }
    if (lane == 0) { g_m[w] = mx; g_dsum[w] = sm; }
}

// ---------------- aggregation (warp per node, gather) ----------------
template<int F, bool RELU>
__global__ void agg_kernel(const float* __restrict__ xw,
                           const float* __restrict__ bias,
                           float* __restrict__ out, int n)
{
    int w = (blockIdx.x * blockDim.x + threadIdx.x) >> 5;
    int lane = threadIdx.x & 31;
    if (w >= n) return;
    int beg = g_off[w], end = g_off[w + 1];
    float adi = g_adst[w];
    float mi  = g_m[w];
    float inv = 1.f / g_dsum[w];
    float4 acc0 = make_float4(0.f, 0.f, 0.f, 0.f);
    float4 acc1 = make_float4(0.f, 0.f, 0.f, 0.f);
    for (int k = beg; k < end; k++) {
        int s = g_csrc[k];
        float e = g_asrc[s] + adi;
        e = e >= 0.f ? e : 0.2f * e;
        float att = __expf(e - mi) * inv;
        const float4* row = (const float4*)(xw + (size_t)s * F);
        float4 v = row[lane];
        acc0.x += att * v.x; acc0.y += att * v.y;
        acc0.z += att * v.z; acc0.w += att * v.w;
        if (F == 256) {
            float4 v1 = row[32 + lane];
            acc1.x += att * v1.x; acc1.y += att * v1.y;
            acc1.z += att * v1.z; acc1.w += att * v1.w;
        }
    }
    const float4* b4 = (const float4*)bias;
    float4 b0 = b4[lane];
    acc0.x += b0.x; acc0.y += b0.y; acc0.z += b0.z; acc0.w += b0.w;
    if (RELU) {
        acc0.x = fmaxf(acc0.x, 0.f); acc0.y = fmaxf(acc0.y, 0.f);
        acc0.z = fmaxf(acc0.z, 0.f); acc0.w = fmaxf(acc0.w, 0.f);
    }
    float4* o4 = (float4*)(out + (size_t)w * F);
    o4[lane] = acc0;
    if (F == 256) {
        float4 b1v = b4[32 + lane];
        acc1.x += b1v.x; acc1.y += b1v.y; acc1.z += b1v.z; acc1.w += b1v.w;
        if (RELU) {
            acc1.x = fmaxf(acc1.x, 0.f); acc1.y = fmaxf(acc1.y, 0.f);
            acc1.z = fmaxf(acc1.z, 0.f); acc1.w = fmaxf(acc1.w, 0.f);
        }
        o4[32 + lane] = acc1;
    }
}

// ---------------- launch ----------------
extern "C" void kernel_launch(void* const* d_in, const int* in_sizes, int n_in,
                              void* d_out, int out_size) {
    const float* x   = (const float*)d_in[0];
    const int*   ei  = (const int*)d_in[1];
    const float* W1  = (const float*)d_in[2];
    const float* a1s = (const float*)d_in[3];
    const float* a1d = (const float*)d_in[4];
    const float* b1  = (const float*)d_in[5];
    const float* W2  = (const float*)d_in[6];
    const float* a2s = (const float*)d_in[7];
    const float* a2d = (const float*)d_in[8];
    const float* b2  = (const float*)d_in[9];
    float* out = (float*)d_out;

    int n = in_sizes[0] / 128;        // 50000
    int E = in_sizes[1] / 2;          // 800000

    float *p_xw = nullptr, *p_h = nullptr;
    __nv_bfloat16 *p_ah = nullptr, *p_al = nullptr, *p_bh = nullptr, *p_bl = nullptr;
    cudaGetSymbolAddress((void**)&p_xw, g_xw);
    cudaGetSymbolAddress((void**)&p_h,  g_h);
    cudaGetSymbolAddress((void**)&p_ah, g_ah);
    cudaGetSymbolAddress((void**)&p_al, g_al);
    cudaGetSymbolAddress((void**)&p_bh, g_bhw);
    cudaGetSymbolAddress((void**)&p_bl, g_blw);

    int nblk    = (n + 255) / 256;
    int eblk    = (E + 255) / 256;
    int warpBlk = (n * 32 + 255) / 256;
    int sblk    = (n + 1023) / 1024;    // 49
    dim3 g1((n + GBM - 1) / GBM, 256 / GBN);
    dim3 g2((n + GBM - 1) / GBM, 128 / GBN);

    // dtype sniff + CSR build
    detect_kernel<<<1, 32>>>(ei);
    init_cnt_kernel<<<nblk, 256>>>(n);
    hist_kernel<<<eblk, 256>>>(ei, E);
    blockscan_kernel<<<sblk, 1024>>>(n);
    scanb_kernel<<<1, 32>>>(sblk);
    addoff_kernel<<<sblk, 1024>>>(n);
    selfloop_kernel<<<nblk, 256>>>(n);
    scatter_kernel<<<eblk, 256>>>(ei, E);

    // ---- layer 1: Fin=128 -> H=256, relu ----
    split_kernel<<<(n * 128 / 4 + 255) / 256, 256>>>(x,  p_ah, p_al, n * 128 / 4);
    split_kernel<<<(128 * 256 / 4 + 255) / 256, 256>>>(W1, p_bh, p_bl, 128 * 256 / 4);
    gemm_wmma_kernel<<<g1, 256>>>(p_ah, p_al, p_bh, p_bl, p_xw, n, 128, 256);
    alpha_kernel<256><<<warpBlk, 256>>>(p_xw, a1s, a1d, n);
    stats_kernel<<<warpBlk, 256>>>(n);
    agg_kernel<256, true><<<warpBlk, 256>>>(p_xw, b1, p_h, n);

    // ---- layer 2: H=256 -> Fout=128, no relu ----
    split_kernel<<<(n * 256 / 4 + 255) / 256, 256>>>(p_h, p_ah, p_al, n * 256 / 4);
    split_kernel<<<(256 * 128 / 4 + 255) / 256, 256>>>(W2, p_bh, p_bl, 256 * 128 / 4);
    gemm_wmma_kernel<<<g2, 256>>>(p_ah, p_al, p_bh, p_bl, p_xw, n, 256, 128);
    alpha_kernel<128><<<warpBlk, 256>>>(p_xw, a2s, a2d, n);
    stats_kernel<<<warpBlk, 256>>>(n);
    agg_kernel<128, false><<<warpBlk, 256>>>(p_xw, b2, out, n);
}

// round 3
// speedup vs baseline: 1.3167x; 1.0244x over previous
#include <cuda_runtime.h>
#include <cuda_bf16.h>
#include <mma.h>
#include <math.h>

using namespace nvcuda;

// ---------------- problem constants ----------------
#define MAXN 50000
#define NPAD 50048              // padded rows: wmma C stores never OOB (scratch only)
#define MAXE 800000
#define MAXTOT (MAXE + MAXN)

// ---------------- device scratch ----------------
__device__ float g_xw[(size_t)NPAD * 256];   // xw of current layer (fp32)
__device__ float g_h[(size_t)NPAD * 256];    // layer-1 output
__device__ float g_asrc[MAXN];
__device__ float g_adst[MAXN];
__device__ float g_att[MAXTOT];              // normalized attention per CSR edge
__device__ int   g_cnt[MAXN];
__device__ int   g_off[MAXN + 1];
__device__ int   g_csrc[MAXTOT];
__device__ int   g_bsum[64];
__device__ int   g_total;
__device__ int   g_is64;

// ---------------- dtype detection ----------------
__global__ void detect_kernel(const int* __restrict__ ei) {
    if (threadIdx.x == 0 && blockIdx.x == 0) {
        int z = 1;
        #pragma unroll
        for (int i = 1; i < 64; i += 2)
            if (ei[i] != 0) z = 0;
        g_is64 = z;
    }
}

__device__ __forceinline__ int load_idx(const int* __restrict__ ei, long long elem, int is64) {
    return is64 ? ei[2 * elem] : ei[elem];
}

// ---------------- CSR build ----------------
__global__ void init_kernel(int n) {   // cnt=1 (self loop), zero alpha accumulators
    int i = blockIdx.x * blockDim.x + threadIdx.x;
    if (i < n) { g_cnt[i] = 1; g_asrc[i] = 0.f; g_adst[i] = 0.f; }
}

__global__ void zero_alpha_kernel(int n) {
    int i = blockIdx.x * blockDim.x + threadIdx.x;
    if (i < n) { g_asrc[i] = 0.f; g_adst[i] = 0.f; }
}

__global__ void hist_kernel(const int* __restrict__ ei, int E) {
    int i = blockIdx.x * blockDim.x + threadIdx.x;
    if (i >= E) return;
    int d = load_idx(ei, (long long)E + i, g_is64);
    atomicAdd(&g_cnt[d], 1);
}

__global__ __launch_bounds__(1024) void blockscan_kernel(int n) {
    __shared__ int warpsum[32];
    int i = blockIdx.x * 1024 + threadIdx.x;
    int v = (i < n) ? g_cnt[i] : 0;
    int lane = threadIdx.x & 31, wid = threadIdx.x >> 5;
    int s = v;
    #pragma unroll
    for (int o = 1; o < 32; o <<= 1) {
        int t = __shfl_up_sync(~0u, s, o);
        if (lane >= o) s += t;
    }
    if (lane == 31) warpsum[wid] = s;
    __syncthreads();
    if (wid == 0) {
        int ws = warpsum[lane];
        #pragma unroll
        for (int o = 1; o < 32; o <<= 1) {
            int t = __shfl_up_sync(~0u, ws, o);
            if (lane >= o) ws += t;
        }
        warpsum[lane] = ws;
    }
    __syncthreads();
    int excl = s - v + (wid ? warpsum[wid - 1] : 0);
    if (i < n) g_off[i] = excl;
    if (threadIdx.x == 1023) g_bsum[blockIdx.x] = excl + v;
}

__global__ void scanb_kernel(int nb) {
    if (threadIdx.x == 0 && blockIdx.x == 0) {
        int run = 0;
        for (int b = 0; b < nb; b++) { int t = g_bsum[b]; g_bsum[b] = run; run += t; }
        g_total = run;
    }
}

// add block offsets + write self loop + init cursor
__global__ void finish_off_kernel(int n) {
    int i = blockIdx.x * 1024 + threadIdx.x;
    if (i < n) {
        int off = g_off[i] + g_bsum[i >> 10];
        g_off[i] = off;
        g_csrc[off] = i;       // self loop first
        g_cnt[i] = off + 1;    // cursor
    }
    if (i == 0) g_off[n] = g_total;
}

__global__ void scatter_kernel(const int* __restrict__ ei, int E) {
    int i = blockIdx.x * blockDim.x + threadIdx.x;
    if (i >= E) return;
    int is64 = g_is64;
    int s = load_idx(ei, i, is64);
    int d = load_idx(ei, (long long)E + i, is64);
    int p = atomicAdd(&g_cnt[d], 1);
    g_csrc[p] = s;
}

// ---------------- GEMM: fp32 in, hi/lo bf16 wmma, fused alpha epilogue -------
#define GBM 128
#define GBN 64
#define LDA 24
#define LDB 72
#define LDC 68

// smem layout (aliased): stage region then C region
// sAh: 128*24*2 = 6144 | sAl: 6144 | sBh: 16*72*2 = 2304 | sBl: 2304  => 16896
// sC : 128*68*4 = 34816  (used only after K loop)
#define SMEM_BYTES 34816

__global__ __launch_bounds__(256) void gemm_fused_kernel(
    const float* __restrict__ A, const float* __restrict__ B,
    float* __restrict__ C,
    const float* __restrict__ avs, const float* __restrict__ avd,
    int M, int K, int N)
{
    __shared__ __align__(16) char buf[SMEM_BYTES];
    __nv_bfloat16* sAh = (__nv_bfloat16*)(buf);
    __nv_bfloat16* sAl = (__nv_bfloat16*)(buf + 6144);
    __nv_bfloat16* sBh = (__nv_bfloat16*)(buf + 12288);
    __nv_bfloat16* sBl = (__nv_bfloat16*)(buf + 14592);
    float*         sC  = (float*)(buf);

    int r0 = blockIdx.x * GBM, c0 = blockIdx.y * GBN;
    int tid = threadIdx.x;
    int wid = tid >> 5, lane = tid & 31;

    wmma::fragment<wmma::accumulator, 16, 16, 16, float> acc[4];
    #pragma unroll
    for (int j = 0; j < 4; j++) wmma::fill_fragment(acc[j], 0.f);

    int a_row = tid >> 1, a_c = (tid & 1) * 8;   // 8 floats per thread
    int b_row = tid >> 4, b_c = (tid & 15) * 4;  // 4 floats per thread

    for (int k0 = 0; k0 < K; k0 += 16) {
        {   // A tile 128x16: load fp32, split hi/lo to bf16
            int gr = r0 + a_row;
            float4 v0 = make_float4(0.f,0.f,0.f,0.f), v1 = v0;
            if (gr < M) {
                const float* ap = A + (size_t)gr * K + k0 + a_c;
                v0 = *(const float4*)ap;
                v1 = *(const float4*)(ap + 4);
            }
            float vs[8] = {v0.x,v0.y,v0.z,v0.w,v1.x,v1.y,v1.z,v1.w};
            __nv_bfloat16 hs[8], ls[8];
            #pragma unroll
            for (int q = 0; q < 8; q++) {
                hs[q] = __float2bfloat16(vs[q]);
                ls[q] = __float2bfloat16(vs[q] - __bfloat162float(hs[q]));
            }
            *(uint4*)&sAh[a_row * LDA + a_c] = *(uint4*)hs;
            *(uint4*)&sAl[a_row * LDA + a_c] = *(uint4*)ls;
        }
        {   // B tile 16x64
            float4 v = *(const float4*)(B + (size_t)(k0 + b_row) * N + c0 + b_c);
            float vs[4] = {v.x,v.y,v.z,v.w};
            __nv_bfloat16 hs[4], ls[4];
            #pragma unroll
            for (int q = 0; q < 4; q++) {
                hs[q] = __float2bfloat16(vs[q]);
                ls[q] = __float2bfloat16(vs[q] - __bfloat162float(hs[q]));
            }
            *(uint2*)&sBh[b_row * LDB + b_c] = *(uint2*)hs;
            *(uint2*)&sBl[b_row * LDB + b_c] = *(uint2*)ls;
        }
        __syncthreads();
        wmma::fragment<wmma::matrix_a, 16, 16, 16, __nv_bfloat16, wmma::row_major> fah, fal;
        wmma::load_matrix_sync(fah, &sAh[(wid * 16) * LDA], LDA);
        wmma::load_matrix_sync(fal, &sAl[(wid * 16) * LDA], LDA);
        #pragma unroll
        for (int j = 0; j < 4; j++) {
            wmma::fragment<wmma::matrix_b, 16, 16, 16, __nv_bfloat16, wmma::row_major> fbh, fbl;
            wmma::load_matrix_sync(fbh, &sBh[j * 16], LDB);
            wmma::load_matrix_sync(fbl, &sBl[j * 16], LDB);
            wmma::mma_sync(acc[j], fah, fbh, acc[j]);
            wmma::mma_sync(acc[j], fah, fbl, acc[j]);
            wmma::mma_sync(acc[j], fal, fbh, acc[j]);
        }
        __syncthreads();
    }

    // stage C tile to smem (aliases stage buffers — all reads done)
    #pragma unroll
    for (int j = 0; j < 4; j++)
        wmma::store_matrix_sync(&sC[(wid * 16) * LDC + j * 16], acc[j], LDC, wmma::mem_row_major);
    __syncthreads();

    // write C to global: thread t -> row t>>1, 32 cols
    {
        int row = tid >> 1, cb = (tid & 1) * 32;
        float* gp = C + (size_t)(r0 + row) * N + c0 + cb;   // C padded to NPAD rows
        const float* sp = &sC[row * LDC + cb];
        #pragma unroll
        for (int q = 0; q < 8; q++)
            *(float4*)(gp + 4 * q) = *(const float4*)(sp + 4 * q);
    }

    // fused alpha partials: warp wid owns rows wid*16 .. wid*16+15
    {
        float as0 = avs[c0 + 2 * lane], as1 = avs[c0 + 2 * lane + 1];
        float ad0 = avd[c0 + 2 * lane], ad1 = avd[c0 + 2 * lane + 1];
        #pragma unroll
        for (int r = 0; r < 16; r++) {
            int row = wid * 16 + r;
            float x0 = sC[row * LDC + 2 * lane];
            float x1 = sC[row * LDC + 2 * lane + 1];
            float ss = x0 * as0 + x1 * as1;
            float sd = x0 * ad0 + x1 * ad1;
            #pragma unroll
            for (int o = 16; o; o >>= 1) {
                ss += __shfl_xor_sync(~0u, ss, o);
                sd += __shfl_xor_sync(~0u, sd, o);
            }
            int gr = r0 + row;
            if (lane == 0 && gr < M) {
                atomicAdd(&g_asrc[gr], ss);
                atomicAdd(&g_adst[gr], sd);
            }
        }
    }
}

// ---------------- segment softmax: stats + normalized att per edge ----------
__global__ void stats_kernel(int n) {
    int w = (blockIdx.x * blockDim.x + threadIdx.x) >> 5;
    int lane = threadIdx.x & 31;
    if (w >= n) return;
    int beg = g_off[w], end = g_off[w + 1];
    float adi = g_adst[w];
    float mx = -1e30f, sm = 0.f;
    for (int k = beg + lane; k < end; k += 32) {
        int s = g_csrc[k];
        float e = g_asrc[s] + adi;
        e = e >= 0.f ? e : 0.2f * e;
        if (e > mx) { sm = sm * __expf(mx - e) + 1.f; mx = e; }
        else        { sm += __expf(e - mx); }
    }
    #pragma unroll
    for (int o = 16; o; o >>= 1) {
        float mo = __shfl_xor_sync(~0u, mx, o);
        float so = __shfl_xor_sync(~0u, sm, o);
        float nm = fmaxf(mx, mo);
        sm = sm * __expf(mx - nm) + so * __expf(mo - nm);
        mx = nm;
    }
    float inv = 1.f / sm;
    // second pass: write normalized att (asrc re-reads are L1-warm)
    for (int k = beg + lane; k < end; k += 32) {
        int s = g_csrc[k];
        float e = g_asrc[s] + adi;
        e = e >= 0.f ? e : 0.2f * e;
        g_att[k] = __expf(e - mx) * inv;
    }
}

// ---------------- aggregation (warp per node, pure gather) ------------------
template<int F, bool RELU>
__global__ void agg_kernel(const float* __restrict__ xw,
                           const float* __restrict__ bias,
                           float* __restrict__ out, int n)
{
    int w = (blockIdx.x * blockDim.x + threadIdx.x) >> 5;
    int lane = threadIdx.x & 31;
    if (w >= n) return;
    int beg = g_off[w], end = g_off[w + 1];
    float4 acc0 = make_float4(0.f, 0.f, 0.f, 0.f);
    float4 acc1 = make_float4(0.f, 0.f, 0.f, 0.f);
    int k = beg;
    for (; k + 2 <= end; k += 2) {
        int s0 = g_csrc[k], s1 = g_csrc[k + 1];
        float a0 = g_att[k], a1 = g_att[k + 1];
        const float4* r0p = (const float4*)(xw + (size_t)s0 * F);
        const float4* r1p = (const float4*)(xw + (size_t)s1 * F);
        float4 v0 = r0p[lane];
        float4 v1 = r1p[lane];
        acc0.x += a0 * v0.x + a1 * v1.x;
        acc0.y += a0 * v0.y + a1 * v1.y;
        acc0.z += a0 * v0.z + a1 * v1.z;
        acc0.w += a0 * v0.w + a1 * v1.w;
        if (F == 256) {
            float4 u0 = r0p[32 + lane];
            float4 u1 = r1p[32 + lane];
            acc1.x += a0 * u0.x + a1 * u1.x;
            acc1.y += a0 * u0.y + a1 * u1.y;
            acc1.z += a0 * u0.z + a1 * u1.z;
            acc1.w += a0 * u0.w + a1 * u1.w;
        }
    }
    if (k < end) {
        int s0 = g_csrc[k];
        float a0 = g_att[k];
        const float4* r0p = (const float4*)(xw + (size_t)s0 * F);
        float4 v0 = r0p[lane];
        acc0.x += a0 * v0.x; acc0.y += a0 * v0.y;
        acc0.z += a0 * v0.z; acc0.w += a0 * v0.w;
        if (F == 256) {
            float4 u0 = r0p[32 + lane];
            acc1.x += a0 * u0.x; acc1.y += a0 * u0.y;
            acc1.z += a0 * u0.z; acc1.w += a0 * u0.w;
        }
    }
    const float4* b4 = (const float4*)bias;
    float4 b0 = b4[lane];
    acc0.x += b0.x; acc0.y += b0.y; acc0.z += b0.z; acc0.w += b0.w;
    if (RELU) {
        acc0.x = fmaxf(acc0.x, 0.f); acc0.y = fmaxf(acc0.y, 0.f);
        acc0.z = fmaxf(acc0.z, 0.f); acc0.w = fmaxf(acc0.w, 0.f);
    }
    float4* o4 = (float4*)(out + (size_t)w * F);
    o4[lane] = acc0;
    if (F == 256) {
        float4 b1v = b4[32 + lane];
        acc1.x += b1v.x; acc1.y += b1v.y; acc1.z += b1v.z; acc1.w += b1v.w;
        if (RELU) {
            acc1.x = fmaxf(acc1.x, 0.f); acc1.y = fmaxf(acc1.y, 0.f);
            acc1.z = fmaxf(acc1.z, 0.f); acc1.w = fmaxf(acc1.w, 0.f);
        }
        o4[32 + lane] = acc1;
    }
}

// ---------------- launch ----------------
extern "C" void kernel_launch(void* const* d_in, const int* in_sizes, int n_in,
                              void* d_out, int out_size) {
    const float* x   = (const float*)d_in[0];
    const int*   ei  = (const int*)d_in[1];
    const float* W1  = (const float*)d_in[2];
    const float* a1s = (const float*)d_in[3];
    const float* a1d = (const float*)d_in[4];
    const float* b1  = (const float*)d_in[5];
    const float* W2  = (const float*)d_in[6];
    const float* a2s = (const float*)d_in[7];
    const float* a2d = (const float*)d_in[8];
    const float* b2  = (const float*)d_in[9];
    float* out = (float*)d_out;

    int n = in_sizes[0] / 128;        // 50000
    int E = in_sizes[1] / 2;          // 800000

    float *p_xw = nullptr, *p_h = nullptr;
    cudaGetSymbolAddress((void**)&p_xw, g_xw);
    cudaGetSymbolAddress((void**)&p_h,  g_h);

    int nblk    = (n + 255) / 256;
    int eblk    = (E + 255) / 256;
    int warpBlk = (n * 32 + 255) / 256;
    int sblk    = (n + 1023) / 1024;
    dim3 g1((n + GBM - 1) / GBM, 256 / GBN);
    dim3 g2((n + GBM - 1) / GBM, 128 / GBN);

    // dtype sniff + CSR build
    detect_kernel<<<1, 32>>>(ei);
    init_kernel<<<nblk, 256>>>(n);
    hist_kernel<<<eblk, 256>>>(ei, E);
    blockscan_kernel<<<sblk, 1024>>>(n);
    scanb_kernel<<<1, 32>>>(sblk);
    finish_off_kernel<<<sblk, 1024>>>(n);
    scatter_kernel<<<eblk, 256>>>(ei, E);

    // ---- layer 1: Fin=128 -> H=256, relu ----
    gemm_fused_kernel<<<g1, 256>>>(x, W1, p_xw, a1s, a1d, n, 128, 256);
    stats_kernel<<<warpBlk, 256>>>(n);
    agg_kernel<256, true><<<warpBlk, 256>>>(p_xw, b1, p_h, n);

    // ---- layer 2: H=256 -> Fout=128, no relu ----
    zero_alpha_kernel<<<nblk, 256>>>(n);
    gemm_fused_kernel<<<g2, 256>>>(p_h, W2, p_xw, a2s, a2d, n, 256, 128);
    stats_kernel<<<warpBlk, 256>>>(n);
    agg_kernel<128, false><<<warpBlk, 256>>>(p_xw, b2, out, n);
}

// round 4
// speedup vs baseline: 1.3353x; 1.0141x over previous
#include <cuda_runtime.h>
#include <cuda_bf16.h>
#include <mma.h>
#include <math.h>

using namespace nvcuda;

// ---------------- problem constants ----------------
#define MAXN 50000
#define NPAD 50048              // 391*128: GEMM C stores never OOB (scratch only)
#define MAXE 800000
#define MAXTOT (MAXE + MAXN)

// ---------------- device scratch ----------------
__device__ float g_xw[(size_t)NPAD * 256];   // xw of current layer (fp32)
__device__ float g_h[(size_t)NPAD * 256];    // layer-1 output
__device__ float g_asrc[MAXN];
__device__ float g_adst[MAXN];
__device__ float g_att[MAXTOT];              // normalized attention per CSR edge
__device__ int   g_cnt[MAXN];
__device__ int   g_off[MAXN + 1];
__device__ int   g_csrc[MAXTOT];
__device__ int   g_bsum[64];
__device__ int   g_total;
__device__ int   g_is64;

// ---------------- dtype detection ----------------
__global__ void detect_kernel(const int* __restrict__ ei) {
    if (threadIdx.x == 0 && blockIdx.x == 0) {
        int z = 1;
        #pragma unroll
        for (int i = 1; i < 64; i += 2)
            if (ei[i] != 0) z = 0;
        g_is64 = z;
    }
}

__device__ __forceinline__ int load_idx(const int* __restrict__ ei, long long elem, int is64) {
    return is64 ? ei[2 * elem] : ei[elem];
}

// ---------------- CSR build ----------------
__global__ void init_kernel(int n) {
    int i = blockIdx.x * blockDim.x + threadIdx.x;
    if (i < n) { g_cnt[i] = 1; g_asrc[i] = 0.f; g_adst[i] = 0.f; }
}

__global__ void zero_alpha_kernel(int n) {
    int i = blockIdx.x * blockDim.x + threadIdx.x;
    if (i < n) { g_asrc[i] = 0.f; g_adst[i] = 0.f; }
}

__global__ void hist_kernel(const int* __restrict__ ei, int E) {
    int i = blockIdx.x * blockDim.x + threadIdx.x;
    if (i >= E) return;
    int d = load_idx(ei, (long long)E + i, g_is64);
    atomicAdd(&g_cnt[d], 1);
}

__global__ __launch_bounds__(1024) void blockscan_kernel(int n) {
    __shared__ int warpsum[32];
    int i = blockIdx.x * 1024 + threadIdx.x;
    int v = (i < n) ? g_cnt[i] : 0;
    int lane = threadIdx.x & 31, wid = threadIdx.x >> 5;
    int s = v;
    #pragma unroll
    for (int o = 1; o < 32; o <<= 1) {
        int t = __shfl_up_sync(~0u, s, o);
        if (lane >= o) s += t;
    }
    if (lane == 31) warpsum[wid] = s;
    __syncthreads();
    if (wid == 0) {
        int ws = warpsum[lane];
        #pragma unroll
        for (int o = 1; o < 32; o <<= 1) {
            int t = __shfl_up_sync(~0u, ws, o);
            if (lane >= o) ws += t;
        }
        warpsum[lane] = ws;
    }
    __syncthreads();
    int excl = s - v + (wid ? warpsum[wid - 1] : 0);
    if (i < n) g_off[i] = excl;
    if (threadIdx.x == 1023) g_bsum[blockIdx.x] = excl + v;
}

__global__ void scanb_kernel(int nb) {
    if (threadIdx.x == 0 && blockIdx.x == 0) {
        int run = 0;
        for (int b = 0; b < nb; b++) { int t = g_bsum[b]; g_bsum[b] = run; run += t; }
        g_total = run;
    }
}

__global__ void finish_off_kernel(int n) {
    int i = blockIdx.x * 1024 + threadIdx.x;
    if (i < n) {
        int off = g_off[i] + g_bsum[i >> 10];
        g_off[i] = off;
        g_csrc[off] = i;       // self loop first
        g_cnt[i] = off + 1;    // cursor
    }
    if (i == 0) g_off[n] = g_total;
}

__global__ void scatter_kernel(const int* __restrict__ ei, int E) {
    int i = blockIdx.x * blockDim.x + threadIdx.x;
    if (i >= E) return;
    int is64 = g_is64;
    int s = load_idx(ei, i, is64);
    int d = load_idx(ei, (long long)E + i, is64);
    int p = atomicAdd(&g_cnt[d], 1);
    g_csrc[p] = s;
}

// ------- GEMM: 128x128 tile, 8 warps, double-buffered, hi/lo bf16, fused alpha
#define GBM 128
#define GBN 128
#define LDA 24     // bf16 elems per A smem row (16 data + 8 pad)
#define LDB 136    // bf16 elems per B smem row (128 data + 8 pad)
// per-stage bytes: Ah 128*24*2=6144, Al 6144, Bh 16*136*2=4352, Bl 4352 -> 20992
#define STAGE_BYTES 20992

__global__ __launch_bounds__(256, 1) void gemm_fused_kernel(
    const float* __restrict__ A, const float* __restrict__ B,
    float* __restrict__ C,
    const float* __restrict__ avs, const float* __restrict__ avd,
    int M, int K, int N)
{
    __shared__ __align__(16) char buf[2 * STAGE_BYTES];

    int tid = threadIdx.x;
    int w = tid >> 5, lane = tid & 31;
    int wr = w >> 2, wc = w & 3;             // warp grid 2x4
    int r0 = blockIdx.x * GBM, c0 = blockIdx.y * GBN;

    wmma::fragment<wmma::accumulator, 16, 16, 16, float> acc[4][2];
    #pragma unroll
    for (int rr = 0; rr < 4; rr++)
        #pragma unroll
        for (int cc = 0; cc < 2; cc++) wmma::fill_fragment(acc[rr][cc], 0.f);

    int a_row = tid >> 1, a_c = (tid & 1) * 8;   // A tile 128x16: 8 floats/thread
    int b_row = tid >> 4, b_c = (tid & 15) * 8;  // B tile 16x128: 8 floats/thread

    float ar[8], br[8];
    // ---- prologue: load tile 0 ----
    {
        int gr = r0 + a_row;
        float4 v0 = make_float4(0.f,0.f,0.f,0.f), v1 = v0;
        if (gr < M) {
            const float* ap = A + (size_t)gr * K + a_c;
            v0 = *(const float4*)ap; v1 = *(const float4*)(ap + 4);
        }
        *(float4*)ar = v0; *(float4*)(ar + 4) = v1;
        const float* bp = B + (size_t)b_row * N + c0 + b_c;
        *(float4*)br = *(const float4*)bp;
        *(float4*)(br + 4) = *(const float4*)(bp + 4);
    }
    int steps = K / 16;
    // store stage 0
    {
        __nv_bfloat16* sAh = (__nv_bfloat16*)(buf);
        __nv_bfloat16* sAl = (__nv_bfloat16*)(buf + 6144);
        __nv_bfloat16* sBh = (__nv_bfloat16*)(buf + 12288);
        __nv_bfloat16* sBl = (__nv_bfloat16*)(buf + 16640);
        __nv_bfloat16 hs[8], ls[8];
        #pragma unroll
        for (int q = 0; q < 8; q++) {
            hs[q] = __float2bfloat16(ar[q]);
            ls[q] = __float2bfloat16(ar[q] - __bfloat162float(hs[q]));
        }
        *(uint4*)&sAh[a_row * LDA + a_c] = *(uint4*)hs;
        *(uint4*)&sAl[a_row * LDA + a_c] = *(uint4*)ls;
        #pragma unroll
        for (int q = 0; q < 8; q++) {
            hs[q] = __float2bfloat16(br[q]);
            ls[q] = __float2bfloat16(br[q] - __bfloat162float(hs[q]));
        }
        *(uint4*)&sBh[b_row * LDB + b_c] = *(uint4*)hs;
        *(uint4*)&sBl[b_row * LDB + b_c] = *(uint4*)ls;
    }
    __syncthreads();

    for (int i = 0; i < steps; i++) {
        int cur = i & 1, nxt = cur ^ 1;
        // prefetch next tile to registers (overlaps with MMA below)
        if (i + 1 < steps) {
            int k0 = (i + 1) * 16;
            int gr = r0 + a_row;
            float4 v0 = make_float4(0.f,0.f,0.f,0.f), v1 = v0;
            if (gr < M) {
                const float* ap = A + (size_t)gr * K + k0 + a_c;
                v0 = *(const float4*)ap; v1 = *(const float4*)(ap + 4);
            }
            *(float4*)ar = v0; *(float4*)(ar + 4) = v1;
            const float* bp = B + (size_t)(k0 + b_row) * N + c0 + b_c;
            *(float4*)br = *(const float4*)bp;
            *(float4*)(br + 4) = *(const float4*)(bp + 4);
        }
        // MMA on current stage
        {
            const char* base = buf + cur * STAGE_BYTES;
            const __nv_bfloat16* sAh = (const __nv_bfloat16*)(base);
            const __nv_bfloat16* sAl = (const __nv_bfloat16*)(base + 6144);
            const __nv_bfloat16* sBh = (const __nv_bfloat16*)(base + 12288);
            const __nv_bfloat16* sBl = (const __nv_bfloat16*)(base + 16640);
            wmma::fragment<wmma::matrix_b, 16, 16, 16, __nv_bfloat16, wmma::row_major> fbh[2], fbl[2];
            #pragma unroll
            for (int cc = 0; cc < 2; cc++) {
                wmma::load_matrix_sync(fbh[cc], &sBh[wc * 32 + cc * 16], LDB);
                wmma::load_matrix_sync(fbl[cc], &sBl[wc * 32 + cc * 16], LDB);
            }
            #pragma unroll
            for (int rr = 0; rr < 4; rr++) {
                wmma::fragment<wmma::matrix_a, 16, 16, 16, __nv_bfloat16, wmma::row_major> fah, fal;
                int arow = (wr * 64 + rr * 16) * LDA;
                wmma::load_matrix_sync(fah, &sAh[arow], LDA);
                wmma::load_matrix_sync(fal, &sAl[arow], LDA);
                #pragma unroll
                for (int cc = 0; cc < 2; cc++) {
                    wmma::mma_sync(acc[rr][cc], fah, fbh[cc], acc[rr][cc]);
                    wmma::mma_sync(acc[rr][cc], fah, fbl[cc], acc[rr][cc]);
                    wmma::mma_sync(acc[rr][cc], fal, fbh[cc], acc[rr][cc]);
                }
            }
        }
        // store prefetched tile into next stage (no conflict with cur reads)
        if (i + 1 < steps) {
            char* base = buf + nxt * STAGE_BYTES;
            __nv_bfloat16* sAh = (__nv_bfloat16*)(base);
            __nv_bfloat16* sAl = (__nv_bfloat16*)(base + 6144);
            __nv_bfloat16* sBh = (__nv_bfloat16*)(base + 12288);
            __nv_bfloat16* sBl = (__nv_bfloat16*)(base + 16640);
            __nv_bfloat16 hs[8], ls[8];
            #pragma unroll
            for (int q = 0; q < 8; q++) {
                hs[q] = __float2bfloat16(ar[q]);
                ls[q] = __float2bfloat16(ar[q] - __bfloat162float(hs[q]));
            }
            *(uint4*)&sAh[a_row * LDA + a_c] = *(uint4*)hs;
            *(uint4*)&sAl[a_row * LDA + a_c] = *(uint4*)ls;
            #pragma unroll
            for (int q = 0; q < 8; q++) {
                hs[q] = __float2bfloat16(br[q]);
                ls[q] = __float2bfloat16(br[q] - __bfloat162float(hs[q]));
            }
            *(uint4*)&sBh[b_row * LDB + b_c] = *(uint4*)hs;
            *(uint4*)&sBl[b_row * LDB + b_c] = *(uint4*)ls;
        }
        __syncthreads();
    }

    // ---- store C fragments directly to global (padded scratch) ----
    #pragma unroll
    for (int rr = 0; rr < 4; rr++)
        #pragma unroll
        for (int cc = 0; cc < 2; cc++) {
            int gr = r0 + wr * 64 + rr * 16;
            int gc = c0 + wc * 32 + cc * 16;
            wmma::store_matrix_sync(C + (size_t)gr * N + gc, acc[rr][cc], N, wmma::mem_row_major);
        }
    __threadfence_block();
    __syncthreads();

    // ---- fused alpha partials: warp w owns tile rows w*16 .. w*16+15 ----
    {
        float4 as4 = ((const float4*)(avs + c0))[lane];
        float4 ad4 = ((const float4*)(avd + c0))[lane];
        #pragma unroll
        for (int r = 0; r < 16; r++) {
            int gr = r0 + w * 16 + r;
            float4 xv = ((const float4*)(C + (size_t)gr * N + c0))[lane];
            float ss = xv.x * as4.x + xv.y * as4.y + xv.z * as4.z + xv.w * as4.w;
            float sd = xv.x * ad4.x + xv.y * ad4.y + xv.z * ad4.z + xv.w * ad4.w;
            #pragma unroll
            for (int o = 16; o; o >>= 1) {
                ss += __shfl_xor_sync(~0u, ss, o);
                sd += __shfl_xor_sync(~0u, sd, o);
            }
            if (lane == 0 && gr < M) {
                atomicAdd(&g_asrc[gr], ss);
                atomicAdd(&g_adst[gr], sd);
            }
        }
    }
}

// ---------------- segment softmax: stats + normalized att per edge ----------
__global__ void stats_kernel(int n) {
    int w = (blockIdx.x * blockDim.x + threadIdx.x) >> 5;
    int lane = threadIdx.x & 31;
    if (w >= n) return;
    int beg = g_off[w], end = g_off[w + 1];
    float adi = g_adst[w];
    float mx = -1e30f, sm = 0.f;
    for (int k = beg + lane; k < end; k += 32) {
        int s = g_csrc[k];
        float e = g_asrc[s] + adi;
        e = e >= 0.f ? e : 0.2f * e;
        if (e > mx) { sm = sm * __expf(mx - e) + 1.f; mx = e; }
        else        { sm += __expf(e - mx); }
    }
    #pragma unroll
    for (int o = 16; o; o >>= 1) {
        float mo = __shfl_xor_sync(~0u, mx, o);
        float so = __shfl_xor_sync(~0u, sm, o);
        float nm = fmaxf(mx, mo);
        sm = sm * __expf(mx - nm) + so * __expf(mo - nm);
        mx = nm;
    }
    float inv = 1.f / sm;
    for (int k = beg + lane; k < end; k += 32) {
        int s = g_csrc[k];
        float e = g_asrc[s] + adi;
        e = e >= 0.f ? e : 0.2f * e;
        g_att[k] = __expf(e - mx) * inv;
    }
}

// ---------------- aggregation (warp per node, pure gather) ------------------
template<int F, bool RELU>
__global__ void agg_kernel(const float* __restrict__ xw,
                           const float* __restrict__ bias,
                           float* __restrict__ out, int n)
{
    int w = (blockIdx.x * blockDim.x + threadIdx.x) >> 5;
    int lane = threadIdx.x & 31;
    if (w >= n) return;
    int beg = g_off[w], end = g_off[w + 1];
    float4 acc0 = make_float4(0.f, 0.f, 0.f, 0.f);
    float4 acc1 = make_float4(0.f, 0.f, 0.f, 0.f);
    int k = beg;
    for (; k + 2 <= end; k += 2) {
        int s0 = g_csrc[k], s1 = g_csrc[k + 1];
        float a0 = g_att[k], a1 = g_att[k + 1];
        const float4* r0p = (const float4*)(xw + (size_t)s0 * F);
        const float4* r1p = (const float4*)(xw + (size_t)s1 * F);
        float4 v0 = r0p[lane];
        float4 v1 = r1p[lane];
        acc0.x += a0 * v0.x + a1 * v1.x;
        acc0.y += a0 * v0.y + a1 * v1.y;
        acc0.z += a0 * v0.z + a1 * v1.z;
        acc0.w += a0 * v0.w + a1 * v1.w;
        if (F == 256) {
            float4 u0 = r0p[32 + lane];
            float4 u1 = r1p[32 + lane];
            acc1.x += a0 * u0.x + a1 * u1.x;
            acc1.y += a0 * u0.y + a1 * u1.y;
            acc1.z += a0 * u0.z + a1 * u1.z;
            acc1.w += a0 * u0.w + a1 * u1.w;
        }
    }
    if (k < end) {
        int s0 = g_csrc[k];
        float a0 = g_att[k];
        const float4* r0p = (const float4*)(xw + (size_t)s0 * F);
        float4 v0 = r0p[lane];
        acc0.x += a0 * v0.x; acc0.y += a0 * v0.y;
        acc0.z += a0 * v0.z; acc0.w += a0 * v0.w;
        if (F == 256) {
            float4 u0 = r0p[32 + lane];
            acc1.x += a0 * u0.x; acc1.y += a0 * u0.y;
            acc1.z += a0 * u0.z; acc1.w += a0 * u0.w;
        }
    }
    const float4* b4 = (const float4*)bias;
    float4 b0 = b4[lane];
    acc0.x += b0.x; acc0.y += b0.y; acc0.z += b0.z; acc0.w += b0.w;
    if (RELU) {
        acc0.x = fmaxf(acc0.x, 0.f); acc0.y = fmaxf(acc0.y, 0.f);
        acc0.z = fmaxf(acc0.z, 0.f); acc0.w = fmaxf(acc0.w, 0.f);
    }
    float4* o4 = (float4*)(out + (size_t)w * F);
    o4[lane] = acc0;
    if (F == 256) {
        float4 b1v = b4[32 + lane];
        acc1.x += b1v.x; acc1.y += b1v.y; acc1.z += b1v.z; acc1.w += b1v.w;
        if (RELU) {
            acc1.x = fmaxf(acc1.x, 0.f); acc1.y = fmaxf(acc1.y, 0.f);
            acc1.z = fmaxf(acc1.z, 0.f); acc1.w = fmaxf(acc1.w, 0.f);
        }
        o4[32 + lane] = acc1;
    }
}

// ---------------- launch ----------------
extern "C" void kernel_launch(void* const* d_in, const int* in_sizes, int n_in,
                              void* d_out, int out_size) {
    const float* x   = (const float*)d_in[0];
    const int*   ei  = (const int*)d_in[1];
    const float* W1  = (const float*)d_in[2];
    const float* a1s = (const float*)d_in[3];
    const float* a1d = (const float*)d_in[4];
    const float* b1  = (const float*)d_in[5];
    const float* W2  = (const float*)d_in[6];
    const float* a2s = (const float*)d_in[7];
    const float* a2d = (const float*)d_in[8];
    const float* b2  = (const float*)d_in[9];
    float* out = (float*)d_out;

    int n = in_sizes[0] / 128;        // 50000
    int E = in_sizes[1] / 2;          // 800000

    float *p_xw = nullptr, *p_h = nullptr;
    cudaGetSymbolAddress((void**)&p_xw, g_xw);
    cudaGetSymbolAddress((void**)&p_h,  g_h);

    int nblk    = (n + 255) / 256;
    int eblk    = (E + 255) / 256;
    int warpBlk = (n * 32 + 255) / 256;
    int sblk    = (n + 1023) / 1024;
    dim3 g1((n + GBM - 1) / GBM, 256 / GBN);   // (391, 2)
    dim3 g2((n + GBM - 1) / GBM, 128 / GBN);   // (391, 1)

    // order: gemm1 placed early (independent of CSR) -> lands in ncu's slot
    detect_kernel<<<1, 32>>>(ei);
    init_kernel<<<nblk, 256>>>(n);
    hist_kernel<<<eblk, 256>>>(ei, E);
    gemm_fused_kernel<<<g1, 256>>>(x, W1, p_xw, a1s, a1d, n, 128, 256);
    blockscan_kernel<<<sblk, 1024>>>(n);
    scanb_kernel<<<1, 32>>>(sblk);
    finish_off_kernel<<<sblk, 1024>>>(n);
    scatter_kernel<<<eblk, 256>>>(ei, E);

    // ---- layer 1 tail ----
    stats_kernel<<<warpBlk, 256>>>(n);
    zero_alpha_kernel<<<nblk, 256>>>(n);
    agg_kernel<256, true><<<warpBlk, 256>>>(p_xw, b1, p_h, n);

    // ---- layer 2 ----
    gemm_fused_kernel<<<g2, 256>>>(p_h, W2, p_xw, a2s, a2d, n, 256, 128);
    stats_kernel<<<warpBlk, 256>>>(n);
    agg_kernel<128, false><<<warpBlk, 256>>>(p_xw, b2, out, n);
}

// round 5
// speedup vs baseline: 1.3801x; 1.0336x over previous
#include <cuda_runtime.h>
#include <cuda_bf16.h>
#include <mma.h>
#include <math.h>

using namespace nvcuda;

// ---------------- problem constants ----------------
#define MAXN 50000
#define NPAD 50048              // 391*128: GEMM C stores never OOB (scratch only)
#define MAXE 800000
#define MAXTOT (MAXE + MAXN)

// ---------------- device scratch ----------------
__device__ float g_xw[(size_t)NPAD * 256];   // xw of current layer (fp32)
__device__ float g_h[(size_t)NPAD * 256];    // layer-1 output
__device__ float g_asrc[MAXN];
__device__ float g_adst[MAXN];
__device__ float g_att[MAXTOT];              // normalized attention per CSR edge
__device__ int   g_cnt[MAXN];
__device__ int   g_off[MAXN + 1];
__device__ int   g_csrc[MAXTOT];
__device__ int   g_bsum[64];
__device__ int   g_total;
__device__ int   g_is64;

// ---------------- dtype detection ----------------
__global__ void detect_kernel(const int* __restrict__ ei) {
    if (threadIdx.x == 0 && blockIdx.x == 0) {
        int z = 1;
        #pragma unroll
        for (int i = 1; i < 64; i += 2)
            if (ei[i] != 0) z = 0;
        g_is64 = z;
    }
}

__device__ __forceinline__ int load_idx(const int* __restrict__ ei, long long elem, int is64) {
    return is64 ? ei[2 * elem] : ei[elem];
}

// ---------------- CSR build ----------------
__global__ void init_kernel(int n) {
    int i = blockIdx.x * blockDim.x + threadIdx.x;
    if (i < n) { g_cnt[i] = 1; g_asrc[i] = 0.f; g_adst[i] = 0.f; }
}

__global__ void zero_alpha_kernel(int n) {
    int i = blockIdx.x * blockDim.x + threadIdx.x;
    if (i < n) { g_asrc[i] = 0.f; g_adst[i] = 0.f; }
}

__global__ void hist_kernel(const int* __restrict__ ei, int E) {
    int i = blockIdx.x * blockDim.x + threadIdx.x;
    if (i >= E) return;
    int d = load_idx(ei, (long long)E + i, g_is64);
    atomicAdd(&g_cnt[d], 1);
}

__global__ __launch_bounds__(1024) void blockscan_kernel(int n) {
    __shared__ int warpsum[32];
    int i = blockIdx.x * 1024 + threadIdx.x;
    int v = (i < n) ? g_cnt[i] : 0;
    int lane = threadIdx.x & 31, wid = threadIdx.x >> 5;
    int s = v;
    #pragma unroll
    for (int o = 1; o < 32; o <<= 1) {
        int t = __shfl_up_sync(~0u, s, o);
        if (lane >= o) s += t;
    }
    if (lane == 31) warpsum[wid] = s;
    __syncthreads();
    if (wid == 0) {
        int ws = warpsum[lane];
        #pragma unroll
        for (int o = 1; o < 32; o <<= 1) {
            int t = __shfl_up_sync(~0u, ws, o);
            if (lane >= o) ws += t;
        }
        warpsum[lane] = ws;
    }
    __syncthreads();
    int excl = s - v + (wid ? warpsum[wid - 1] : 0);
    if (i < n) g_off[i] = excl;
    if (threadIdx.x == 1023) g_bsum[blockIdx.x] = excl + v;
}

__global__ void scanb_kernel(int nb) {
    if (threadIdx.x == 0 && blockIdx.x == 0) {
        int run = 0;
        for (int b = 0; b < nb; b++) { int t = g_bsum[b]; g_bsum[b] = run; run += t; }
        g_total = run;
    }
}

__global__ void finish_off_kernel(int n) {
    int i = blockIdx.x * 1024 + threadIdx.x;
    if (i < n) {
        int off = g_off[i] + g_bsum[i >> 10];
        g_off[i] = off;
        g_csrc[off] = i;       // self loop first
        g_cnt[i] = off + 1;    // cursor
    }
    if (i == 0) g_off[n] = g_total;
}

__global__ void scatter_kernel(const int* __restrict__ ei, int E) {
    int i = blockIdx.x * blockDim.x + threadIdx.x;
    if (i >= E) return;
    int is64 = g_is64;
    int s = load_idx(ei, i, is64);
    int d = load_idx(ei, (long long)E + i, is64);
    int p = atomicAdd(&g_cnt[d], 1);
    g_csrc[p] = s;
}

// ------- GEMM: 128x64 tile, 8 warps (4x2), 2 CTA/SM, dbl-buffered, hi/lo bf16
#define GBM 128
#define GBN 64
#define LDA 24     // bf16 per A smem row (16 data + 8 pad)
#define LDB 72     // bf16 per B smem row (64 data + 8 pad)
// stage: Ah 128*24*2=6144, Al 6144, Bh 16*72*2=2304, Bl 2304 -> 16896
#define STAGE_BYTES 16896

__global__ __launch_bounds__(256, 2) void gemm_fused_kernel(
    const float* __restrict__ A, const float* __restrict__ B,
    float* __restrict__ C,
    const float* __restrict__ avs, const float* __restrict__ avd,
    int M, int K, int N)
{
    __shared__ __align__(16) char buf[2 * STAGE_BYTES];

    int tid = threadIdx.x;
    int w = tid >> 5, lane = tid & 31;
    int wr = w >> 1, wc = w & 1;             // warp grid 4x2, each warp 32x32
    int r0 = blockIdx.x * GBM, c0 = blockIdx.y * GBN;

    wmma::fragment<wmma::accumulator, 16, 16, 16, float> acc[2][2];
    #pragma unroll
    for (int rr = 0; rr < 2; rr++)
        #pragma unroll
        for (int cc = 0; cc < 2; cc++) wmma::fill_fragment(acc[rr][cc], 0.f);

    int a_row = tid >> 1, a_c = (tid & 1) * 8;   // A tile 128x16: 8 floats/thread
    int b_row = tid >> 4, b_c = (tid & 15) * 4;  // B tile 16x64: 4 floats/thread

    float ar[8], br[4];
    {   // prologue load tile 0
        int gr = r0 + a_row;
        float4 v0 = make_float4(0.f,0.f,0.f,0.f), v1 = v0;
        if (gr < M) {
            const float* ap = A + (size_t)gr * K + a_c;
            v0 = *(const float4*)ap; v1 = *(const float4*)(ap + 4);
        }
        *(float4*)ar = v0; *(float4*)(ar + 4) = v1;
        *(float4*)br = *(const float4*)(B + (size_t)b_row * N + c0 + b_c);
    }
    int steps = K / 16;
    {   // store stage 0
        __nv_bfloat16* sAh = (__nv_bfloat16*)(buf);
        __nv_bfloat16* sAl = (__nv_bfloat16*)(buf + 6144);
        __nv_bfloat16* sBh = (__nv_bfloat16*)(buf + 12288);
        __nv_bfloat16* sBl = (__nv_bfloat16*)(buf + 14592);
        __nv_bfloat16 hs[8], ls[8];
        #pragma unroll
        for (int q = 0; q < 8; q++) {
            hs[q] = __float2bfloat16(ar[q]);
            ls[q] = __float2bfloat16(ar[q] - __bfloat162float(hs[q]));
        }
        *(uint4*)&sAh[a_row * LDA + a_c] = *(uint4*)hs;
        *(uint4*)&sAl[a_row * LDA + a_c] = *(uint4*)ls;
        #pragma unroll
        for (int q = 0; q < 4; q++) {
            hs[q] = __float2bfloat16(br[q]);
            ls[q] = __float2bfloat16(br[q] - __bfloat162float(hs[q]));
        }
        *(uint2*)&sBh[b_row * LDB + b_c] = *(uint2*)hs;
        *(uint2*)&sBl[b_row * LDB + b_c] = *(uint2*)ls;
    }
    __syncthreads();

    for (int i = 0; i < steps; i++) {
        int cur = i & 1, nxt = cur ^ 1;
        if (i + 1 < steps) {   // register prefetch (overlaps MMAs)
            int k0 = (i + 1) * 16;
            int gr = r0 + a_row;
            float4 v0 = make_float4(0.f,0.f,0.f,0.f), v1 = v0;
            if (gr < M) {
                const float* ap = A + (size_t)gr * K + k0 + a_c;
                v0 = *(const float4*)ap; v1 = *(const float4*)(ap + 4);
            }
            *(float4*)ar = v0; *(float4*)(ar + 4) = v1;
            *(float4*)br = *(const float4*)(B + (size_t)(k0 + b_row) * N + c0 + b_c);
        }
        {   // MMAs on current stage
            const char* base = buf + cur * STAGE_BYTES;
            const __nv_bfloat16* sAh = (const __nv_bfloat16*)(base);
            const __nv_bfloat16* sAl = (const __nv_bfloat16*)(base + 6144);
            const __nv_bfloat16* sBh = (const __nv_bfloat16*)(base + 12288);
            const __nv_bfloat16* sBl = (const __nv_bfloat16*)(base + 14592);
            wmma::fragment<wmma::matrix_b, 16, 16, 16, __nv_bfloat16, wmma::row_major> fbh[2], fbl[2];
            #pragma unroll
            for (int cc = 0; cc < 2; cc++) {
                wmma::load_matrix_sync(fbh[cc], &sBh[wc * 32 + cc * 16], LDB);
                wmma::load_matrix_sync(fbl[cc], &sBl[wc * 32 + cc * 16], LDB);
            }
            #pragma unroll
            for (int rr = 0; rr < 2; rr++) {
                wmma::fragment<wmma::matrix_a, 16, 16, 16, __nv_bfloat16, wmma::row_major> fah, fal;
                int arow = (wr * 32 + rr * 16) * LDA;
                wmma::load_matrix_sync(fah, &sAh[arow], LDA);
                wmma::load_matrix_sync(fal, &sAl[arow], LDA);
                #pragma unroll
                for (int cc = 0; cc < 2; cc++) {
                    wmma::mma_sync(acc[rr][cc], fah, fbh[cc], acc[rr][cc]);
                    wmma::mma_sync(acc[rr][cc], fah, fbl[cc], acc[rr][cc]);
                    wmma::mma_sync(acc[rr][cc], fal, fbh[cc], acc[rr][cc]);
                }
            }
        }
        if (i + 1 < steps) {   // commit prefetched tile to next stage
            char* base = buf + nxt * STAGE_BYTES;
            __nv_bfloat16* sAh = (__nv_bfloat16*)(base);
            __nv_bfloat16* sAl = (__nv_bfloat16*)(base + 6144);
            __nv_bfloat16* sBh = (__nv_bfloat16*)(base + 12288);
            __nv_bfloat16* sBl = (__nv_bfloat16*)(base + 14592);
            __nv_bfloat16 hs[8], ls[8];
            #pragma unroll
            for (int q = 0; q < 8; q++) {
                hs[q] = __float2bfloat16(ar[q]);
                ls[q] = __float2bfloat16(ar[q] - __bfloat162float(hs[q]));
            }
            *(uint4*)&sAh[a_row * LDA + a_c] = *(uint4*)hs;
            *(uint4*)&sAl[a_row * LDA + a_c] = *(uint4*)ls;
            #pragma unroll
            for (int q = 0; q < 4; q++) {
                hs[q] = __float2bfloat16(br[q]);
                ls[q] = __float2bfloat16(br[q] - __bfloat162float(hs[q]));
            }
            *(uint2*)&sBh[b_row * LDB + b_c] = *(uint2*)hs;
            *(uint2*)&sBl[b_row * LDB + b_c] = *(uint2*)ls;
        }
        __syncthreads();
    }

    // ---- store C fragments directly to global (padded scratch) ----
    #pragma unroll
    for (int rr = 0; rr < 2; rr++)
        #pragma unroll
        for (int cc = 0; cc < 2; cc++) {
            int gr = r0 + wr * 32 + rr * 16;
            int gc = c0 + wc * 32 + cc * 16;
            wmma::store_matrix_sync(C + (size_t)gr * N + gc, acc[rr][cc], N, wmma::mem_row_major);
        }
    __syncthreads();

    // ---- fused alpha partials over this 64-col slice; warp w owns 16 rows ----
    {
        float2 as2 = ((const float2*)(avs + c0))[lane];
        float2 ad2 = ((const float2*)(avd + c0))[lane];
        #pragma unroll
        for (int r = 0; r < 16; r++) {
            int gr = r0 + w * 16 + r;
            float2 xv = ((const float2*)(C + (size_t)gr * N + c0))[lane];
            float ss = xv.x * as2.x + xv.y * as2.y;
            float sd = xv.x * ad2.x + xv.y * ad2.y;
            #pragma unroll
            for (int o = 16; o; o >>= 1) {
                ss += __shfl_xor_sync(~0u, ss, o);
                sd += __shfl_xor_sync(~0u, sd, o);
            }
            if (lane == 0 && gr < M) {
                atomicAdd(&g_asrc[gr], ss);
                atomicAdd(&g_adst[gr], sd);
            }
        }
    }
}

// ---------------- segment softmax: stats + normalized att per edge ----------
__global__ void stats_kernel(int n) {
    int w = (blockIdx.x * blockDim.x + threadIdx.x) >> 5;
    int lane = threadIdx.x & 31;
    if (w >= n) return;
    int beg = g_off[w], end = g_off[w + 1];
    float adi = g_adst[w];
    float mx = -1e30f, sm = 0.f;
    for (int k = beg + lane; k < end; k += 32) {
        int s = g_csrc[k];
        float e = g_asrc[s] + adi;
        e = e >= 0.f ? e : 0.2f * e;
        if (e > mx) { sm = sm * __expf(mx - e) + 1.f; mx = e; }
        else        { sm += __expf(e - mx); }
    }
    #pragma unroll
    for (int o = 16; o; o >>= 1) {
        float mo = __shfl_xor_sync(~0u, mx, o);
        float so = __shfl_xor_sync(~0u, sm, o);
        float nm = fmaxf(mx, mo);
        sm = sm * __expf(mx - nm) + so * __expf(mo - nm);
        mx = nm;
    }
    float inv = 1.f / sm;
    for (int k = beg + lane; k < end; k += 32) {
        int s = g_csrc[k];
        float e = g_asrc[s] + adi;
        e = e >= 0.f ? e : 0.2f * e;
        g_att[k] = __expf(e - mx) * inv;
    }
}

// ---------------- aggregation (warp per node, pure gather) ------------------
template<int F, bool RELU>
__global__ void agg_kernel(const float* __restrict__ xw,
                           const float* __restrict__ bias,
                           float* __restrict__ out, int n)
{
    int w = (blockIdx.x * blockDim.x + threadIdx.x) >> 5;
    int lane = threadIdx.x & 31;
    if (w >= n) return;
    int beg = g_off[w], end = g_off[w + 1];
    float4 acc0 = make_float4(0.f, 0.f, 0.f, 0.f);
    float4 acc1 = make_float4(0.f, 0.f, 0.f, 0.f);
    int k = beg;
    for (; k + 2 <= end; k += 2) {
        int s0 = g_csrc[k], s1 = g_csrc[k + 1];
        float a0 = g_att[k], a1 = g_att[k + 1];
        const float4* r0p = (const float4*)(xw + (size_t)s0 * F);
        const float4* r1p = (const float4*)(xw + (size_t)s1 * F);
        float4 v0 = r0p[lane];
        float4 v1 = r1p[lane];
        acc0.x += a0 * v0.x + a1 * v1.x;
        acc0.y += a0 * v0.y + a1 * v1.y;
        acc0.z += a0 * v0.z + a1 * v1.z;
        acc0.w += a0 * v0.w + a1 * v1.w;
        if (F == 256) {
            float4 u0 = r0p[32 + lane];
            float4 u1 = r1p[32 + lane];
            acc1.x += a0 * u0.x + a1 * u1.x;
            acc1.y += a0 * u0.y + a1 * u1.y;
            acc1.z += a0 * u0.z + a1 * u1.z;
            acc1.w += a0 * u0.w + a1 * u1.w;
        }
    }
    if (k < end) {
        int s0 = g_csrc[k];
        float a0 = g_att[k];
        const float4* r0p = (const float4*)(xw + (size_t)s0 * F);
        float4 v0 = r0p[lane];
        acc0.x += a0 * v0.x; acc0.y += a0 * v0.y;
        acc0.z += a0 * v0.z; acc0.w += a0 * v0.w;
        if (F == 256) {
            float4 u0 = r0p[32 + lane];
            acc1.x += a0 * u0.x; acc1.y += a0 * u0.y;
            acc1.z += a0 * u0.z; acc1.w += a0 * u0.w;
        }
    }
    const float4* b4 = (const float4*)bias;
    float4 b0 = b4[lane];
    acc0.x += b0.x; acc0.y += b0.y; acc0.z += b0.z; acc0.w += b0.w;
    if (RELU) {
        acc0.x = fmaxf(acc0.x, 0.f); acc0.y = fmaxf(acc0.y, 0.f);
        acc0.z = fmaxf(acc0.z, 0.f); acc0.w = fmaxf(acc0.w, 0.f);
    }
    float4* o4 = (float4*)(out + (size_t)w * F);
    o4[lane] = acc0;
    if (F == 256) {
        float4 b1v = b4[32 + lane];
        acc1.x += b1v.x; acc1.y += b1v.y; acc1.z += b1v.z; acc1.w += b1v.w;
        if (RELU) {
            acc1.x = fmaxf(acc1.x, 0.f); acc1.y = fmaxf(acc1.y, 0.f);
            acc1.z = fmaxf(acc1.z, 0.f); acc1.w = fmaxf(acc1.w, 0.f);
        }
        o4[32 + lane] = acc1;
    }
}

// ---------------- launch ----------------
extern "C" void kernel_launch(void* const* d_in, const int* in_sizes, int n_in,
                              void* d_out, int out_size) {
    const float* x   = (const float*)d_in[0];
    const int*   ei  = (const int*)d_in[1];
    const float* W1  = (const float*)d_in[2];
    const float* a1s = (const float*)d_in[3];
    const float* a1d = (const float*)d_in[4];
    const float* b1  = (const float*)d_in[5];
    const float* W2  = (const float*)d_in[6];
    const float* a2s = (const float*)d_in[7];
    const float* a2d = (const float*)d_in[8];
    const float* b2  = (const float*)d_in[9];
    float* out = (float*)d_out;

    int n = in_sizes[0] / 128;        // 50000
    int E = in_sizes[1] / 2;          // 800000

    float *p_xw = nullptr, *p_h = nullptr;
    cudaGetSymbolAddress((void**)&p_xw, g_xw);
    cudaGetSymbolAddress((void**)&p_h,  g_h);

    int nblk    = (n + 255) / 256;
    int eblk    = (E + 255) / 256;
    int warpBlk = (n * 32 + 255) / 256;
    int sblk    = (n + 1023) / 1024;
    dim3 g1((n + GBM - 1) / GBM, 256 / GBN);   // (391, 4)
    dim3 g2((n + GBM - 1) / GBM, 128 / GBN);   // (391, 2)

    // gemm1 in profiled slot (4th launch)
    detect_kernel<<<1, 32>>>(ei);
    init_kernel<<<nblk, 256>>>(n);
    hist_kernel<<<eblk, 256>>>(ei, E);
    gemm_fused_kernel<<<g1, 256>>>(x, W1, p_xw, a1s, a1d, n, 128, 256);
    blockscan_kernel<<<sblk, 1024>>>(n);
    scanb_kernel<<<1, 32>>>(sblk);
    finish_off_kernel<<<sblk, 1024>>>(n);
    scatter_kernel<<<eblk, 256>>>(ei, E);

    // ---- layer 1 tail ----
    stats_kernel<<<warpBlk, 256>>>(n);
    zero_alpha_kernel<<<nblk, 256>>>(n);
    agg_kernel<256, true><<<warpBlk, 256>>>(p_xw, b1, p_h, n);

    // ---- layer 2 ----
    gemm_fused_kernel<<<g2, 256>>>(p_h, W2, p_xw, a2s, a2d, n, 256, 128);
    stats_kernel<<<warpBlk, 256>>>(n);
    agg_kernel<128, false><<<warpBlk, 256>>>(p_xw, b2, out, n);
}

// round 7
// speedup vs baseline: 1.6315x; 1.1822x over previous
#include <cuda_runtime.h>
#include <cuda_bf16.h>
#include <math.h>
#include <stdint.h>

// ---------------- problem constants ----------------
#define MAXN 50000
#define NPAD 50048              // 391*128 padded rows (scratch only)
#define MAXE 800000
#define MAXTOT (MAXE + MAXN)

// ---------------- device scratch ----------------
__device__ float g_xw[(size_t)NPAD * 256];   // xw of current layer (fp32)
__device__ float g_h[(size_t)NPAD * 256];    // layer-1 output
__device__ __nv_bfloat16 g_bth[32768];       // W^T hi  [N][K]
__device__ __nv_bfloat16 g_btl[32768];       // W^T lo  [N][K]
__device__ float g_asrc[MAXN];
__device__ float g_adst[MAXN];
__device__ float g_att[MAXTOT];
__device__ int   g_cnt[MAXN];
__device__ int   g_off[MAXN + 1];
__device__ int   g_csrc[MAXTOT];
__device__ int   g_bsum[64];
__device__ int   g_total;
__device__ int   g_is64;

// ---------------- mma / ldmatrix helpers (sm_80+ ops, compile on compute_103) --
__device__ __forceinline__ uint32_t smem_u32(const void* p) {
    uint32_t a;
    asm("{ .reg .u64 t; cvta.to.shared.u64 t, %1; cvt.u32.u64 %0, t; }" : "=r"(a) : "l"(p));
    return a;
}
__device__ __forceinline__ void ldsm4(uint32_t* r, uint32_t addr) {
    asm volatile("ldmatrix.sync.aligned.m8n8.x4.shared.b16 {%0,%1,%2,%3}, [%4];"
        : "=r"(r[0]), "=r"(r[1]), "=r"(r[2]), "=r"(r[3]) : "r"(addr));
}
__device__ __forceinline__ void mma16816(float* c, const uint32_t* a, const uint32_t* b) {
    asm volatile("mma.sync.aligned.m16n8k16.row.col.f32.bf16.bf16.f32 "
        "{%0,%1,%2,%3}, {%4,%5,%6,%7}, {%8,%9}, {%0,%1,%2,%3};"
        : "+f"(c[0]), "+f"(c[1]), "+f"(c[2]), "+f"(c[3])
        : "r"(a[0]), "r"(a[1]), "r"(a[2]), "r"(a[3]), "r"(b[0]), "r"(b[1]));
}

// ---------------- dtype detection ----------------
__global__ void detect_kernel(const int* __restrict__ ei) {
    if (threadIdx.x == 0 && blockIdx.x == 0) {
        int z = 1;
        #pragma unroll
        for (int i = 1; i < 64; i += 2)
            if (ei[i] != 0) z = 0;
        g_is64 = z;
    }
}
__device__ __forceinline__ int load_idx(const int* __restrict__ ei, long long elem, int is64) {
    return is64 ? ei[2 * elem] : ei[elem];
}

// ---------------- CSR build ----------------
__global__ void init_kernel(int n) {
    int i = blockIdx.x * blockDim.x + threadIdx.x;
    if (i < n) { g_cnt[i] = 1; g_asrc[i] = 0.f; g_adst[i] = 0.f; }
}
__global__ void zero_alpha_kernel(int n) {
    int i = blockIdx.x * blockDim.x + threadIdx.x;
    if (i < n) { g_asrc[i] = 0.f; g_adst[i] = 0.f; }
}
__global__ void hist_kernel(const int* __restrict__ ei, int E) {
    int i = blockIdx.x * blockDim.x + threadIdx.x;
    if (i >= E) return;
    int d = load_idx(ei, (long long)E + i, g_is64);
    atomicAdd(&g_cnt[d], 1);
}
__global__ __launch_bounds__(1024) void blockscan_kernel(int n) {
    __shared__ int warpsum[32];
    int i = blockIdx.x * 1024 + threadIdx.x;
    int v = (i < n) ? g_cnt[i] : 0;
    int lane = threadIdx.x & 31, wid = threadIdx.x >> 5;
    int s = v;
    #pragma unroll
    for (int o = 1; o < 32; o <<= 1) {
        int t = __shfl_up_sync(~0u, s, o);
        if (lane >= o) s += t;
    }
    if (lane == 31) warpsum[wid] = s;
    __syncthreads();
    if (wid == 0) {
        int ws = warpsum[lane];
        #pragma unroll
        for (int o = 1; o < 32; o <<= 1) {
            int t = __shfl_up_sync(~0u, ws, o);
            if (lane >= o) ws += t;
        }
        warpsum[lane] = ws;
    }
    __syncthreads();
    int excl = s - v + (wid ? warpsum[wid - 1] : 0);
    if (i < n) g_off[i] = excl;
    if (threadIdx.x == 1023) g_bsum[blockIdx.x] = excl + v;
}
__global__ void scanb_kernel(int nb) {
    if (threadIdx.x == 0 && blockIdx.x == 0) {
        int run = 0;
        for (int b = 0; b < nb; b++) { int t = g_bsum[b]; g_bsum[b] = run; run += t; }
        g_total = run;
    }
}
__global__ void finish_off_kernel(int n) {
    int i = blockIdx.x * 1024 + threadIdx.x;
    if (i < n) {
        int off = g_off[i] + g_bsum[i >> 10];
        g_off[i] = off;
        g_csrc[off] = i;
        g_cnt[i] = off + 1;
    }
    if (i == 0) g_off[n] = g_total;
}
__global__ void scatter_kernel(const int* __restrict__ ei, int E) {
    int i = blockIdx.x * blockDim.x + threadIdx.x;
    if (i >= E) return;
    int is64 = g_is64;
    int s = load_idx(ei, i, is64);
    int d = load_idx(ei, (long long)E + i, is64);
    int p = atomicAdd(&g_cnt[d], 1);
    g_csrc[p] = s;
}

// ---------------- W^T split: W[K][N] fp32 -> g_bth/g_btl [N][K] bf16 ----------
__global__ void wt_split_kernel(const float* __restrict__ W, int K, int N) {
    int i = blockIdx.x * blockDim.x + threadIdx.x;
    if (i >= N * K) return;
    int nn = i / K, kk = i - nn * K;
    float v = W[(size_t)kk * N + nn];
    __nv_bfloat16 h = __float2bfloat16(v);
    g_bth[i] = h;
    g_btl[i] = __float2bfloat16(v - __bfloat162float(h));
}

// ---- GEMM: 128x64 tile, 8 warps (warp 32x32), mma.sync+ldmatrix, hi/lo bf16 --
// smem per stage (bytes): Ah 128*48=6144 @0 | Al 6144 @6144 | Bh 64*48=3072 @12288
//                         | Bl 3072 @15360  -> 18432
#define LDAB 48            // bytes per smem row (16 bf16 data + 8 pad)
#define OFF_AL 6144
#define OFF_BH 12288
#define OFF_BL 15360
#define STAGE_B 18432

__global__ __launch_bounds__(256, 2) void gemm_mma_kernel(
    const float* __restrict__ A, int Kfull,
    const __nv_bfloat16* __restrict__ Bth, const __nv_bfloat16* __restrict__ Btl,
    float* __restrict__ C,
    const float* __restrict__ avs, const float* __restrict__ avd,
    int M, int N)
{
    __shared__ __align__(16) char buf[2 * STAGE_B];
    uint32_t sb = smem_u32(buf);

    int tid = threadIdx.x;
    int w = tid >> 5, lane = tid & 31;
    int wr = w >> 1, wc = w & 1;                 // warp tile 32(M) x 32(N)
    int r0 = blockIdx.x * 128, c0 = blockIdx.y * 64;

    float acc[2][4][4];
    #pragma unroll
    for (int mt = 0; mt < 2; mt++)
        #pragma unroll
        for (int nt = 0; nt < 4; nt++)
            #pragma unroll
            for (int q = 0; q < 4; q++) acc[mt][nt][q] = 0.f;

    // staging maps
    int a_row = tid >> 1, a_half = (tid & 1) * 8;       // A: 8 fp32 per thread
    int b_row = tid & 63, b_sel = tid >> 6;             // B: uint4 per thread
    int b_khalf = b_sel & 1, b_hilo = b_sel >> 1;

    // ldmatrix lane addresses (byte offsets within a stage)
    int la_row = (lane & 15), la_k = (lane >> 4) * 8;            // A frag
    int lb_n   = (lane & 7) + ((lane >> 4) & 1) * 8;             // B frag (16n x k16)
    int lb_k   = ((lane >> 3) & 1) * 8;
    uint32_t a_frag_off = (uint32_t)(la_row * LDAB + la_k * 2);
    uint32_t b_frag_off = (uint32_t)(lb_n * LDAB + lb_k * 2);

    float arv[8];
    uint4 brv;
    int steps = Kfull / 16;

    // ---- prologue: load k-step 0 to registers ----
    {
        int gr = r0 + a_row;
        float4 v0 = make_float4(0.f,0.f,0.f,0.f), v1 = v0;
        if (gr < M) {
            const float* ap = A + (size_t)gr * Kfull + a_half;
            v0 = *(const float4*)ap; v1 = *(const float4*)(ap + 4);
        }
        *(float4*)arv = v0; *(float4*)(arv + 4) = v1;
        const __nv_bfloat16* bp = (b_hilo ? Btl : Bth) + (size_t)(c0 + b_row) * Kfull + b_khalf * 8;
        brv = *(const uint4*)bp;
    }
    // store stage 0
    {
        char* st = buf;
        __nv_bfloat16 hs[8], ls[8];
        #pragma unroll
        for (int q = 0; q < 8; q++) {
            hs[q] = __float2bfloat16(arv[q]);
            ls[q] = __float2bfloat16(arv[q] - __bfloat162float(hs[q]));
        }
        *(uint4*)(st + a_row * LDAB + a_half * 2)          = *(uint4*)hs;
        *(uint4*)(st + OFF_AL + a_row * LDAB + a_half * 2) = *(uint4*)ls;
        *(uint4*)(st + (b_hilo ? OFF_BL : OFF_BH) + b_row * LDAB + b_khalf * 16) = brv;
    }
    __syncthreads();

    for (int i = 0; i < steps; i++) {
        int cur = i & 1, nxt = cur ^ 1;
        if (i + 1 < steps) {   // register prefetch of next k-step
            int k0 = (i + 1) * 16;
            int gr = r0 + a_row;
            float4 v0 = make_float4(0.f,0.f,0.f,0.f), v1 = v0;
            if (gr < M) {
                const float* ap = A + (size_t)gr * Kfull + k0 + a_half;
                v0 = *(const float4*)ap; v1 = *(const float4*)(ap + 4);
            }
            *(float4*)arv = v0; *(float4*)(arv + 4) = v1;
            const __nv_bfloat16* bp = (b_hilo ? Btl : Bth)
                + (size_t)(c0 + b_row) * Kfull + k0 + b_khalf * 8;
            brv = *(const uint4*)bp;
        }
        {   // compute on current stage
            uint32_t st = sb + cur * STAGE_B;
            uint32_t ah[2][4], al[2][4], bh[2][4], bl[2][4];
            #pragma unroll
            for (int mt = 0; mt < 2; mt++) {
                uint32_t rbase = st + (uint32_t)((wr * 32 + mt * 16) * LDAB) + a_frag_off;
                ldsm4(ah[mt], rbase);
                ldsm4(al[mt], rbase + OFF_AL);
            }
            #pragma unroll
            for (int np = 0; np < 2; np++) {
                uint32_t nbase = st + OFF_BH + (uint32_t)((wc * 32 + np * 16) * LDAB) + b_frag_off;
                ldsm4(bh[np], nbase);
                ldsm4(bl[np], nbase + (OFF_BL - OFF_BH));
            }
            #pragma unroll
            for (int mt = 0; mt < 2; mt++)
                #pragma unroll
                for (int nt = 0; nt < 4; nt++) {
                    const uint32_t* bhp = &bh[nt >> 1][(nt & 1) * 2];
                    const uint32_t* blp = &bl[nt >> 1][(nt & 1) * 2];
                    mma16816(acc[mt][nt], ah[mt], bhp);
                    mma16816(acc[mt][nt], ah[mt], blp);
                    mma16816(acc[mt][nt], al[mt], bhp);
                }
        }
        if (i + 1 < steps) {   // commit prefetched k-step to next stage
            char* st = buf + nxt * STAGE_B;
            __nv_bfloat16 hs[8], ls[8];
            #pragma unroll
            for (int q = 0; q < 8; q++) {
                hs[q] = __float2bfloat16(arv[q]);
                ls[q] = __float2bfloat16(arv[q] - __bfloat162float(hs[q]));
            }
            *(uint4*)(st + a_row * LDAB + a_half * 2)          = *(uint4*)hs;
            *(uint4*)(st + OFF_AL + a_row * LDAB + a_half * 2) = *(uint4*)ls;
            *(uint4*)(st + (b_hilo ? OFF_BL : OFF_BH) + b_row * LDAB + b_khalf * 16) = brv;
        }
        __syncthreads();
    }

    // ---- store C + fused alpha partials straight from accumulators ----
    {
        // per-thread columns: col = c0 + wc*32 + nt*8 + (lane&3)*2 (+0,+1)
        float as[4][2], ad[4][2];
        #pragma unroll
        for (int nt = 0; nt < 4; nt++) {
            int col = c0 + wc * 32 + nt * 8 + (lane & 3) * 2;
            as[nt][0] = avs[col];     as[nt][1] = avs[col + 1];
            ad[nt][0] = avd[col];     ad[nt][1] = avd[col + 1];
        }
        #pragma unroll
        for (int mt = 0; mt < 2; mt++) {
            int rA = r0 + wr * 32 + mt * 16 + (lane >> 2);   // rows lane/4 and +8
            int rB = rA + 8;
            float ssA = 0.f, sdA = 0.f, ssB = 0.f, sdB = 0.f;
            #pragma unroll
            for (int nt = 0; nt < 4; nt++) {
                float* c = acc[mt][nt];
                int col = c0 + wc * 32 + nt * 8 + (lane & 3) * 2;
                *(float2*)(C + (size_t)rA * N + col) = make_float2(c[0], c[1]);
                *(float2*)(C + (size_t)rB * N + col) = make_float2(c[2], c[3]);
                ssA += c[0] * as[nt][0] + c[1] * as[nt][1];
                sdA += c[0] * ad[nt][0] + c[1] * ad[nt][1];
                ssB += c[2] * as[nt][0] + c[3] * as[nt][1];
                sdB += c[2] * ad[nt][0] + c[3] * ad[nt][1];
            }
            // reduce over the 4 lanes sharing a row (lane&3 group)
            #pragma unroll
            for (int o = 1; o < 4; o <<= 1) {
                ssA += __shfl_xor_sync(~0u, ssA, o);
                sdA += __shfl_xor_sync(~0u, sdA, o);
                ssB += __shfl_xor_sync(~0u, ssB, o);
                sdB += __shfl_xor_sync(~0u, sdB, o);
            }
            if ((lane & 3) == 0) {
                if (rA < M) { atomicAdd(&g_asrc[rA], ssA); atomicAdd(&g_adst[rA], sdA); }
                if (rB < M) { atomicAdd(&g_asrc[rB], ssB); atomicAdd(&g_adst[rB], sdB); }
            }
        }
    }
}

// ---------------- segment softmax: stats + normalized att per edge ----------
__global__ void stats_kernel(int n) {
    int w = (blockIdx.x * blockDim.x + threadIdx.x) >> 5;
    int lane = threadIdx.x & 31;
    if (w >= n) return;
    int beg = g_off[w], end = g_off[w + 1];
    float adi = g_adst[w];
    float mx = -1e30f, sm = 0.f;
    for (int k = beg + lane; k < end; k += 32) {
        int s = g_csrc[k];
        float e = g_asrc[s] + adi;
        e = e >= 0.f ? e : 0.2f * e;
        if (e > mx) { sm = sm * __expf(mx - e) + 1.f; mx = e; }
        else        { sm += __expf(e - mx); }
    }
    #pragma unroll
    for (int o = 16; o; o >>= 1) {
        float mo = __shfl_xor_sync(~0u, mx, o);
        float so = __shfl_xor_sync(~0u, sm, o);
        float nm = fmaxf(mx, mo);
        sm = sm * __expf(mx - nm) + so * __expf(mo - nm);
        mx = nm;
    }
    float inv = 1.f / sm;
    for (int k = beg + lane; k < end; k += 32) {
        int s = g_csrc[k];
        float e = g_asrc[s] + adi;
        e = e >= 0.f ? e : 0.2f * e;
        g_att[k] = __expf(e - mx) * inv;
    }
}

// ---------------- aggregation (warp per node, pure gather) ------------------
template<int F, bool RELU>
__global__ void agg_kernel(const float* __restrict__ xw,
                           const float* __restrict__ bias,
                           float* __restrict__ out, int n)
{
    int w = (blockIdx.x * blockDim.x + threadIdx.x) >> 5;
    int lane = threadIdx.x & 31;
    if (w >= n) return;
    int beg = g_off[w], end = g_off[w + 1];
    float4 acc0 = make_float4(0.f, 0.f, 0.f, 0.f);
    float4 acc1 = make_float4(0.f, 0.f, 0.f, 0.f);
    int k = beg;
    for (; k + 2 <= end; k += 2) {
        int s0 = g_csrc[k], s1 = g_csrc[k + 1];
        float a0 = g_att[k], a1 = g_att[k + 1];
        const float4* r0p = (const float4*)(xw + (size_t)s0 * F);
        const float4* r1p = (const float4*)(xw + (size_t)s1 * F);
        float4 v0 = r0p[lane];
        float4 v1 = r1p[lane];
        acc0.x += a0 * v0.x + a1 * v1.x;
        acc0.y += a0 * v0.y + a1 * v1.y;
        acc0.z += a0 * v0.z + a1 * v1.z;
        acc0.w += a0 * v0.w + a1 * v1.w;
        if (F == 256) {
            float4 u0 = r0p[32 + lane];
            float4 u1 = r1p[32 + lane];
            acc1.x += a0 * u0.x + a1 * u1.x;
            acc1.y += a0 * u0.y + a1 * u1.y;
            acc1.z += a0 * u0.z + a1 * u1.z;
            acc1.w += a0 * u0.w + a1 * u1.w;
        }
    }
    if (k < end) {
        int s0 = g_csrc[k];
        float a0 = g_att[k];
        const float4* r0p = (const float4*)(xw + (size_t)s0 * F);
        float4 v0 = r0p[lane];
        acc0.x += a0 * v0.x; acc0.y += a0 * v0.y;
        acc0.z += a0 * v0.z; acc0.w += a0 * v0.w;
        if (F == 256) {
            float4 u0 = r0p[32 + lane];
            acc1.x += a0 * u0.x; acc1.y += a0 * u0.y;
            acc1.z += a0 * u0.z; acc1.w += a0 * u0.w;
        }
    }
    const float4* b4 = (const float4*)bias;
    float4 b0 = b4[lane];
    acc0.x += b0.x; acc0.y += b0.y; acc0.z += b0.z; acc0.w += b0.w;
    if (RELU) {
        acc0.x = fmaxf(acc0.x, 0.f); acc0.y = fmaxf(acc0.y, 0.f);
        acc0.z = fmaxf(acc0.z, 0.f); acc0.w = fmaxf(acc0.w, 0.f);
    }
    float4* o4 = (float4*)(out + (size_t)w * F);
    o4[lane] = acc0;
    if (F == 256) {
        float4 b1v = b4[32 + lane];
        acc1.x += b1v.x; acc1.y += b1v.y; acc1.z += b1v.z; acc1.w += b1v.w;
        if (RELU) {
            acc1.x = fmaxf(acc1.x, 0.f); acc1.y = fmaxf(acc1.y, 0.f);
            acc1.z = fmaxf(acc1.z, 0.f); acc1.w = fmaxf(acc1.w, 0.f);
        }
        o4[32 + lane] = acc1;
    }
}

// ---------------- launch ----------------
extern "C" void kernel_launch(void* const* d_in, const int* in_sizes, int n_in,
                              void* d_out, int out_size) {
    const float* x   = (const float*)d_in[0];
    const int*   ei  = (const int*)d_in[1];
    const float* W1  = (const float*)d_in[2];
    const float* a1s = (const float*)d_in[3];
    const float* a1d = (const float*)d_in[4];
    const float* b1  = (const float*)d_in[5];
    const float* W2  = (const float*)d_in[6];
    const float* a2s = (const float*)d_in[7];
    const float* a2d = (const float*)d_in[8];
    const float* b2  = (const float*)d_in[9];
    float* out = (float*)d_out;

    int n = in_sizes[0] / 128;        // 50000
    int E = in_sizes[1] / 2;          // 800000

    float *p_xw = nullptr, *p_h = nullptr;
    __nv_bfloat16 *p_bth = nullptr, *p_btl = nullptr;
    cudaGetSymbolAddress((void**)&p_xw,  g_xw);
    cudaGetSymbolAddress((void**)&p_h,   g_h);
    cudaGetSymbolAddress((void**)&p_bth, g_bth);
    cudaGetSymbolAddress((void**)&p_btl, g_btl);

    int nblk    = (n + 255) / 256;
    int eblk    = (E + 255) / 256;
    int warpBlk = (n * 32 + 255) / 256;
    int sblk    = (n + 1023) / 1024;
    int rtiles  = (n + 127) / 128;    // 391
    dim3 g1(rtiles, 4);               // layer1: N=256 -> 4 col tiles of 64
    dim3 g2(rtiles, 2);               // layer2: N=128 -> 2 col tiles

    // gemm1 lands in ncu's profiled slot (4th launch)
    detect_kernel<<<1, 32>>>(ei);
    init_kernel<<<nblk, 256>>>(n);
    wt_split_kernel<<<(128 * 256 + 255) / 256, 256>>>(W1, 128, 256);
    gemm_mma_kernel<<<g1, 256>>>(x, 128, p_bth, p_btl, p_xw, a1s, a1d, n, 256);
    hist_kernel<<<eblk, 256>>>(ei, E);
    blockscan_kernel<<<sblk, 1024>>>(n);
    scanb_kernel<<<1, 32>>>(sblk);
    finish_off_kernel<<<sblk, 1024>>>(n);
    scatter_kernel<<<eblk, 256>>>(ei, E);

    // ---- layer 1 tail ----
    stats_kernel<<<warpBlk, 256>>>(n);
    zero_alpha_kernel<<<nblk, 256>>>(n);
    agg_kernel<256, true><<<warpBlk, 256>>>(p_xw, b1, p_h, n);

    // ---- layer 2 ----
    wt_split_kernel<<<(256 * 128 + 255) / 256, 256>>>(W2, 256, 128);
    gemm_mma_kernel<<<g2, 256>>>(p_h, 256, p_bth, p_btl, p_xw, a2s, a2d, n, 128);
    stats_kernel<<<warpBlk, 256>>>(n);
    agg_kernel<128, false><<<warpBlk, 256>>>(p_xw, b2, out, n);
}

// round 9
// speedup vs baseline: 1.8232x; 1.1175x over previous
#include <cuda_runtime.h>
#include <cuda_bf16.h>
#include <math.h>
#include <stdint.h>

// ---------------- problem constants ----------------
#define MAXN 50000
#define NPAD 50048              // 391*128 padded rows (scratch only)
#define MAXE 800000
#define MAXTOT (MAXE + MAXN)

// ---------------- device scratch ----------------
__device__ float g_xw[(size_t)NPAD * 256];   // xw of current layer (fp32)
__device__ float g_h[(size_t)NPAD * 256];    // layer-1 output
__device__ __nv_bfloat16 g_bth[32768];       // W^T hi  [N][K]
__device__ __nv_bfloat16 g_btl[32768];       // W^T lo  [N][K]
__device__ float g_asrc[MAXN];
__device__ float g_adst[MAXN];
__device__ float g_att[MAXTOT];
__device__ int   g_cnt[MAXN];
__device__ int   g_off[MAXN + 1];
__device__ int   g_csrc[MAXTOT];
__device__ int   g_bsum[64];
__device__ int   g_total;
__device__ int   g_is64;

// ---------------- mma / ldmatrix helpers ----------------
__device__ __forceinline__ uint32_t smem_u32(const void* p) {
    uint32_t a;
    asm("{ .reg .u64 t; cvta.to.shared.u64 t, %1; cvt.u32.u64 %0, t; }" : "=r"(a) : "l"(p));
    return a;
}
__device__ __forceinline__ void ldsm4(uint32_t* r, uint32_t addr) {
    asm volatile("ldmatrix.sync.aligned.m8n8.x4.shared.b16 {%0,%1,%2,%3}, [%4];"
        : "=r"(r[0]), "=r"(r[1]), "=r"(r[2]), "=r"(r[3]) : "r"(addr));
}
__device__ __forceinline__ void mma16816(float* c, const uint32_t* a, const uint32_t* b) {
    asm volatile("mma.sync.aligned.m16n8k16.row.col.f32.bf16.bf16.f32 "
        "{%0,%1,%2,%3}, {%4,%5,%6,%7}, {%8,%9}, {%0,%1,%2,%3};"
        : "+f"(c[0]), "+f"(c[1]), "+f"(c[2]), "+f"(c[3])
        : "r"(a[0]), "r"(a[1]), "r"(a[2]), "r"(a[3]), "r"(b[0]), "r"(b[1]));
}

// ---------------- dtype detection ----------------
__global__ void detect_kernel(const int* __restrict__ ei) {
    if (threadIdx.x == 0 && blockIdx.x == 0) {
        int z = 1;
        #pragma unroll
        for (int i = 1; i < 64; i += 2)
            if (ei[i] != 0) z = 0;
        g_is64 = z;
    }
}
__device__ __forceinline__ int load_idx(const int* __restrict__ ei, long long elem, int is64) {
    return is64 ? ei[2 * elem] : ei[elem];
}

// ---------------- CSR build ----------------
__global__ void init_kernel(int n) {
    int i = blockIdx.x * blockDim.x + threadIdx.x;
    if (i < n) { g_cnt[i] = 1; g_asrc[i] = 0.f; g_adst[i] = 0.f; }
}
__global__ void zero_alpha_kernel(int n) {
    int i = blockIdx.x * blockDim.x + threadIdx.x;
    if (i < n) { g_asrc[i] = 0.f; g_adst[i] = 0.f; }
}
__global__ void hist_kernel(const int* __restrict__ ei, int E) {
    int i = blockIdx.x * blockDim.x + threadIdx.x;
    if (i >= E) return;
    int d = load_idx(ei, (long long)E + i, g_is64);
    atomicAdd(&g_cnt[d], 1);
}
__global__ __launch_bounds__(1024) void blockscan_kernel(int n) {
    __shared__ int warpsum[32];
    int i = blockIdx.x * 1024 + threadIdx.x;
    int v = (i < n) ? g_cnt[i] : 0;
    int lane = threadIdx.x & 31, wid = threadIdx.x >> 5;
    int s = v;
    #pragma unroll
    for (int o = 1; o < 32; o <<= 1) {
        int t = __shfl_up_sync(~0u, s, o);
        if (lane >= o) s += t;
    }
    if (lane == 31) warpsum[wid] = s;
    __syncthreads();
    if (wid == 0) {
        int ws = warpsum[lane];
        #pragma unroll
        for (int o = 1; o < 32; o <<= 1) {
            int t = __shfl_up_sync(~0u, ws, o);
            if (lane >= o) ws += t;
        }
        warpsum[lane] = ws;
    }
    __syncthreads();
    int excl = s - v + (wid ? warpsum[wid - 1] : 0);
    if (i < n) g_off[i] = excl;
    if (threadIdx.x == 1023) g_bsum[blockIdx.x] = excl + v;
}
__global__ void scanb_kernel(int nb) {
    if (threadIdx.x == 0 && blockIdx.x == 0) {
        int run = 0;
        for (int b = 0; b < nb; b++) { int t = g_bsum[b]; g_bsum[b] = run; run += t; }
        g_total = run;
    }
}
__global__ void finish_off_kernel(int n) {
    int i = blockIdx.x * 1024 + threadIdx.x;
    if (i < n) {
        int off = g_off[i] + g_bsum[i >> 10];
        g_off[i] = off;
        g_csrc[off] = i;
        g_cnt[i] = off + 1;
    }
    if (i == 0) g_off[n] = g_total;
}
__global__ void scatter_kernel(const int* __restrict__ ei, int E) {
    int i = blockIdx.x * blockDim.x + threadIdx.x;
    if (i >= E) return;
    int is64 = g_is64;
    int s = load_idx(ei, i, is64);
    int d = load_idx(ei, (long long)E + i, is64);
    int p = atomicAdd(&g_cnt[d], 1);
    g_csrc[p] = s;
}

// ---------------- W^T split: W[K][N] fp32 -> g_bth/g_btl [N][K] bf16 ----------
__global__ void wt_split_kernel(const float* __restrict__ W, int K, int N) {
    int i = blockIdx.x * blockDim.x + threadIdx.x;
    if (i >= N * K) return;
    int nn = i / K, kk = i - nn * K;
    float v = W[(size_t)kk * N + nn];
    __nv_bfloat16 h = __float2bfloat16(v);
    g_bth[i] = h;
    g_btl[i] = __float2bfloat16(v - __bfloat162float(h));
}

// ---- GEMM: block 128x128, 8 warps (2Mx4N), warp 64x32, mma.sync, hi/lo bf16 --
// stage layout (bytes): Ah 128*48=6144 @0 | Al @6144 | Bh 128*48 @12288 | Bl @18432
#define LDAB 48
#define OFF_AL 6144
#define OFF_BH 12288
#define OFF_BL 18432
#define STAGE_B 24576
#define SMEM_DYN (2 * STAGE_B)

__global__ __launch_bounds__(256, 2) void gemm_mma_kernel(
    const float* __restrict__ A, int Kfull,
    const __nv_bfloat16* __restrict__ Bth, const __nv_bfloat16* __restrict__ Btl,
    float* __restrict__ C,
    const float* __restrict__ avs, const float* __restrict__ avd,
    int M, int N)
{
    extern __shared__ __align__(16) char buf[];
    uint32_t sb = smem_u32(buf);

    int tid = threadIdx.x;
    int w = tid >> 5, lane = tid & 31;
    int wr = w >> 2, wc = w & 3;                 // warp tile 64(M) x 32(N)
    int r0 = blockIdx.x * 128, c0 = blockIdx.y * 128;

    float acc[4][4][4];
    #pragma unroll
    for (int mt = 0; mt < 4; mt++)
        #pragma unroll
        for (int nt = 0; nt < 4; nt++)
            #pragma unroll
            for (int q = 0; q < 4; q++) acc[mt][nt][q] = 0.f;

    // staging maps: both A and B tiles are 128 rows x 16 k
    int s_row = tid >> 1, s_half = (tid & 1) * 8;

    // ldmatrix lane offsets — A pattern (row-major m16k16 fragments)
    int la_row = (lane & 15), la_k = (lane >> 4) * 8;
    uint32_t a_frag_off = (uint32_t)(la_row * LDAB + la_k * 2);
    // B pattern (n16k16 fragments: matrix order n-lo/k-lo, n-lo/k-hi, n-hi/k-lo, n-hi/k-hi)
    int lb_n = (lane & 7) + ((lane >> 4) & 1) * 8;
    int lb_k = ((lane >> 3) & 1) * 8;
    uint32_t b_frag_off = (uint32_t)(lb_n * LDAB + lb_k * 2);

    float arv[8];
    uint4 bh_rv, bl_rv;
    int steps = Kfull / 16;

    // ---- prologue: load k-step 0 ----
    {
        int gr = r0 + s_row;
        float4 v0 = make_float4(0.f,0.f,0.f,0.f), v1 = v0;
        if (gr < M) {
            const float* ap = A + (size_t)gr * Kfull + s_half;
            v0 = *(const float4*)ap; v1 = *(const float4*)(ap + 4);
        }
        *(float4*)arv = v0; *(float4*)(arv + 4) = v1;
        size_t bo = (size_t)(c0 + s_row) * Kfull + s_half;
        bh_rv = *(const uint4*)(Bth + bo);
        bl_rv = *(const uint4*)(Btl + bo);
    }
    {   // store stage 0
        char* st = buf;
        __nv_bfloat16 hs[8], ls[8];
        #pragma unroll
        for (int q = 0; q < 8; q++) {
            hs[q] = __float2bfloat16(arv[q]);
            ls[q] = __float2bfloat16(arv[q] - __bfloat162float(hs[q]));
        }
        *(uint4*)(st + s_row * LDAB + s_half * 2)          = *(uint4*)hs;
        *(uint4*)(st + OFF_AL + s_row * LDAB + s_half * 2) = *(uint4*)ls;
        *(uint4*)(st + OFF_BH + s_row * LDAB + s_half * 2) = bh_rv;
        *(uint4*)(st + OFF_BL + s_row * LDAB + s_half * 2) = bl_rv;
    }
    __syncthreads();

    for (int i = 0; i < steps; i++) {
        int cur = i & 1, nxt = cur ^ 1;
        if (i + 1 < steps) {   // register prefetch of next k-step
            int k0 = (i + 1) * 16;
            int gr = r0 + s_row;
            float4 v0 = make_float4(0.f,0.f,0.f,0.f), v1 = v0;
            if (gr < M) {
                const float* ap = A + (size_t)gr * Kfull + k0 + s_half;
                v0 = *(const float4*)ap; v1 = *(const float4*)(ap + 4);
            }
            *(float4*)arv = v0; *(float4*)(arv + 4) = v1;
            size_t bo = (size_t)(c0 + s_row) * Kfull + k0 + s_half;
            bh_rv = *(const uint4*)(Bth + bo);
            bl_rv = *(const uint4*)(Btl + bo);
        }
        {   // compute on current stage
            uint32_t st = sb + cur * STAGE_B;
            uint32_t bh[2][4], bl[2][4];
            #pragma unroll
            for (int np = 0; np < 2; np++) {
                uint32_t nbase = st + OFF_BH + (uint32_t)((wc * 32 + np * 16) * LDAB) + b_frag_off;
                ldsm4(bh[np], nbase);
                ldsm4(bl[np], nbase + (OFF_BL - OFF_BH));
            }
            #pragma unroll
            for (int mt = 0; mt < 4; mt++) {
                uint32_t ah[4], al[4];
                uint32_t rbase = st + (uint32_t)((wr * 64 + mt * 16) * LDAB) + a_frag_off;
                ldsm4(ah, rbase);
                ldsm4(al, rbase + OFF_AL);
                #pragma unroll
                for (int nt = 0; nt < 4; nt++) {
                    const uint32_t* bhp = &bh[nt >> 1][(nt & 1) * 2];
                    const uint32_t* blp = &bl[nt >> 1][(nt & 1) * 2];
                    mma16816(acc[mt][nt], ah, bhp);
                    mma16816(acc[mt][nt], ah, blp);
                    mma16816(acc[mt][nt], al, bhp);
                }
            }
        }
        if (i + 1 < steps) {   // commit prefetched k-step
            char* st = buf + nxt * STAGE_B;
            __nv_bfloat16 hs[8], ls[8];
            #pragma unroll
            for (int q = 0; q < 8; q++) {
                hs[q] = __float2bfloat16(arv[q]);
                ls[q] = __float2bfloat16(arv[q] - __bfloat162float(hs[q]));
            }
            *(uint4*)(st + s_row * LDAB + s_half * 2)          = *(uint4*)hs;
            *(uint4*)(st + OFF_AL + s_row * LDAB + s_half * 2) = *(uint4*)ls;
            *(uint4*)(st + OFF_BH + s_row * LDAB + s_half * 2) = bh_rv;
            *(uint4*)(st + OFF_BL + s_row * LDAB + s_half * 2) = bl_rv;
        }
        __syncthreads();
    }

    // ---- store C + fused alpha partials straight from accumulators ----
    {
        float as[4][2], ad[4][2];
        #pragma unroll
        for (int nt = 0; nt < 4; nt++) {
            int col = c0 + wc * 32 + nt * 8 + (lane & 3) * 2;
            as[nt][0] = avs[col];     as[nt][1] = avs[col + 1];
            ad[nt][0] = avd[col];     ad[nt][1] = avd[col + 1];
        }
        #pragma unroll
        for (int mt = 0; mt < 4; mt++) {
            int rA = r0 + wr * 64 + mt * 16 + (lane >> 2);
            int rB = rA + 8;
            float ssA = 0.f, sdA = 0.f, ssB = 0.f, sdB = 0.f;
            #pragma unroll
            for (int nt = 0; nt < 4; nt++) {
                float* c = acc[mt][nt];
                int col = c0 + wc * 32 + nt * 8 + (lane & 3) * 2;
                *(float2*)(C + (size_t)rA * N + col) = make_float2(c[0], c[1]);
                *(float2*)(C + (size_t)rB * N + col) = make_float2(c[2], c[3]);
                ssA += c[0] * as[nt][0] + c[1] * as[nt][1];
                sdA += c[0] * ad[nt][0] + c[1] * ad[nt][1];
                ssB += c[2] * as[nt][0] + c[3] * as[nt][1];
                sdB += c[2] * ad[nt][0] + c[3] * ad[nt][1];
            }
            #pragma unroll
            for (int o = 1; o < 4; o <<= 1) {
                ssA += __shfl_xor_sync(~0u, ssA, o);
                sdA += __shfl_xor_sync(~0u, sdA, o);
                ssB += __shfl_xor_sync(~0u, ssB, o);
                sdB += __shfl_xor_sync(~0u, sdB, o);
            }
            if ((lane & 3) == 0) {
                if (rA < M) { atomicAdd(&g_asrc[rA], ssA); atomicAdd(&g_adst[rA], sdA); }
                if (rB < M) { atomicAdd(&g_asrc[rB], ssB); atomicAdd(&g_adst[rB], sdB); }
            }
        }
    }
}

// ---------------- segment softmax: stats + normalized att per edge ----------
__global__ void stats_kernel(int n) {
    int w = (blockIdx.x * blockDim.x + threadIdx.x) >> 5;
    int lane = threadIdx.x & 31;
    if (w >= n) return;
    int beg = g_off[w], end = g_off[w + 1];
    float adi = g_adst[w];
    float mx = -1e30f, sm = 0.f;
    for (int k = beg + lane; k < end; k += 32) {
        int s = g_csrc[k];
        float e = g_asrc[s] + adi;
        e = e >= 0.f ? e : 0.2f * e;
        if (e > mx) { sm = sm * __expf(mx - e) + 1.f; mx = e; }
        else        { sm += __expf(e - mx); }
    }
    #pragma unroll
    for (int o = 16; o; o >>= 1) {
        float mo = __shfl_xor_sync(~0u, mx, o);
        float so = __shfl_xor_sync(~0u, sm, o);
        float nm = fmaxf(mx, mo);
        sm = sm * __expf(mx - nm) + so * __expf(mo - nm);
        mx = nm;
    }
    float inv = 1.f / sm;
    for (int k = beg + lane; k < end; k += 32) {
        int s = g_csrc[k];
        float e = g_asrc[s] + adi;
        e = e >= 0.f ? e : 0.2f * e;
        g_att[k] = __expf(e - mx) * inv;
    }
}

// ---------------- aggregation (warp per node, pure gather) ------------------
template<int F, bool RELU>
__global__ void agg_kernel(const float* __restrict__ xw,
                           const float* __restrict__ bias,
                           float* __restrict__ out, int n)
{
    int w = (blockIdx.x * blockDim.x + threadIdx.x) >> 5;
    int lane = threadIdx.x & 31;
    if (w >= n) return;
    int beg = g_off[w], end = g_off[w + 1];
    float4 acc0 = make_float4(0.f, 0.f, 0.f, 0.f);
    float4 acc1 = make_float4(0.f, 0.f, 0.f, 0.f);
    int k = beg;
    for (; k + 2 <= end; k += 2) {
        int s0 = g_csrc[k], s1 = g_csrc[k + 1];
        float a0 = g_att[k], a1 = g_att[k + 1];
        const float4* r0p = (const float4*)(xw + (size_t)s0 * F);
        const float4* r1p = (const float4*)(xw + (size_t)s1 * F);
        float4 v0 = r0p[lane];
        float4 v1 = r1p[lane];
        acc0.x += a0 * v0.x + a1 * v1.x;
        acc0.y += a0 * v0.y + a1 * v1.y;
        acc0.z += a0 * v0.z + a1 * v1.z;
        acc0.w += a0 * v0.w + a1 * v1.w;
        if (F == 256) {
            float4 u0 = r0p[32 + lane];
            float4 u1 = r1p[32 + lane];
            acc1.x += a0 * u0.x + a1 * u1.x;
            acc1.y += a0 * u0.y + a1 * u1.y;
            acc1.z += a0 * u0.z + a1 * u1.z;
            acc1.w += a0 * u0.w + a1 * u1.w;
        }
    }
    if (k < end) {
        int s0 = g_csrc[k];
        float a0 = g_att[k];
        const float4* r0p = (const float4*)(xw + (size_t)s0 * F);
        float4 v0 = r0p[lane];
        acc0.x += a0 * v0.x; acc0.y += a0 * v0.y;
        acc0.z += a0 * v0.z; acc0.w += a0 * v0.w;
        if (F == 256) {
            float4 u0 = r0p[32 + lane];
            acc1.x += a0 * u0.x; acc1.y += a0 * u0.y;
            acc1.z += a0 * u0.z; acc1.w += a0 * u0.w;
        }
    }
    const float4* b4 = (const float4*)bias;
    float4 b0 = b4[lane];
    acc0.x += b0.x; acc0.y += b0.y; acc0.z += b0.z; acc0.w += b0.w;
    if (RELU) {
        acc0.x = fmaxf(acc0.x, 0.f); acc0.y = fmaxf(acc0.y, 0.f);
        acc0.z = fmaxf(acc0.z, 0.f); acc0.w = fmaxf(acc0.w, 0.f);
    }
    float4* o4 = (float4*)(out + (size_t)w * F);
    o4[lane] = acc0;
    if (F == 256) {
        float4 b1v = b4[32 + lane];
        acc1.x += b1v.x; acc1.y += b1v.y; acc1.z += b1v.z; acc1.w += b1v.w;
        if (RELU) {
            acc1.x = fmaxf(acc1.x, 0.f); acc1.y = fmaxf(acc1.y, 0.f);
            acc1.z = fmaxf(acc1.z, 0.f); acc1.w = fmaxf(acc1.w, 0.f);
        }
        o4[32 + lane] = acc1;
    }
}

// ---------------- launch ----------------
extern "C" void kernel_launch(void* const* d_in, const int* in_sizes, int n_in,
                              void* d_out, int out_size) {
    const float* x   = (const float*)d_in[0];
    const int*   ei  = (const int*)d_in[1];
    const float* W1  = (const float*)d_in[2];
    const float* a1s = (const float*)d_in[3];
    const float* a1d = (const float*)d_in[4];
    const float* b1  = (const float*)d_in[5];
    const float* W2  = (const float*)d_in[6];
    const float* a2s = (const float*)d_in[7];
    const float* a2d = (const float*)d_in[8];
    const float* b2  = (const float*)d_in[9];
    float* out = (float*)d_out;

    int n = in_sizes[0] / 128;        // 50000
    int E = in_sizes[1] / 2;          // 800000

    float *p_xw = nullptr, *p_h = nullptr;
    __nv_bfloat16 *p_bth = nullptr, *p_btl = nullptr;
    cudaGetSymbolAddress((void**)&p_xw,  g_xw);
    cudaGetSymbolAddress((void**)&p_h,   g_h);
    cudaGetSymbolAddress((void**)&p_bth, g_bth);
    cudaGetSymbolAddress((void**)&p_btl, g_btl);

    cudaFuncSetAttribute(gemm_mma_kernel, cudaFuncAttributeMaxDynamicSharedMemorySize, SMEM_DYN);

    int nblk    = (n + 255) / 256;
    int eblk    = (E + 255) / 256;
    int warpBlk = (n * 32 + 255) / 256;
    int sblk    = (n + 1023) / 1024;
    int rtiles  = (n + 127) / 128;    // 391
    dim3 g1(rtiles, 2);               // layer1: N=256 -> 2 col tiles of 128
    dim3 g2(rtiles, 1);               // layer2: N=128 -> 1 col tile

    // gemm1 lands in ncu's profiled slot (4th launch)
    detect_kernel<<<1, 32>>>(ei);
    init_kernel<<<nblk, 256>>>(n);
    wt_split_kernel<<<(128 * 256 + 255) / 256, 256>>>(W1, 128, 256);
    gemm_mma_kernel<<<g1, 256, SMEM_DYN>>>(x, 128, p_bth, p_btl, p_xw, a1s, a1d, n, 256);
    hist_kernel<<<eblk, 256>>>(ei, E);
    blockscan_kernel<<<sblk, 1024>>>(n);
    scanb_kernel<<<1, 32>>>(sblk);
    finish_off_kernel<<<sblk, 1024>>>(n);
    scatter_kernel<<<eblk, 256>>>(ei, E);

    // ---- layer 1 tail ----
    stats_kernel<<<warpBlk, 256>>>(n);
    zero_alpha_kernel<<<nblk, 256>>>(n);
    agg_kernel<256, true><<<warpBlk, 256>>>(p_xw, b1, p_h, n);

    // ---- layer 2 ----
    wt_split_kernel<<<(256 * 128 + 255) / 256, 256>>>(W2, 256, 128);
    gemm_mma_kernel<<<g2, 256, SMEM_DYN>>>(p_h, 256, p_bth, p_btl, p_xw, a2s, a2d, n, 128);
    stats_kernel<<<warpBlk, 256>>>(n);
    agg_kernel<128, false><<<warpBlk, 256>>>(p_xw, b2, out, n);
}

// round 10
// speedup vs baseline: 2.0441x; 1.1212x over previous
#include <cuda_runtime.h>
#include <cuda_bf16.h>
#include <cuda_fp16.h>
#include <math.h>
#include <stdint.h>

// ---------------- problem constants ----------------
#define MAXN 50000
#define NPAD 50048              // 391*128 padded rows (scratch only)
#define MAXE 800000
#define MAXTOT (MAXE + MAXN)

// ---------------- device scratch ----------------
__device__ __half g_xwh[(size_t)NPAD * 256]; // xw of current layer (fp16, gathered)
__device__ float g_h[(size_t)NPAD * 256];    // layer-1 output (fp32, streamed)
__device__ __nv_bfloat16 g_bth[32768];       // W^T hi  [N][K]
__device__ __nv_bfloat16 g_btl[32768];       // W^T lo  [N][K]
__device__ float g_asrc[MAXN];
__device__ float g_adst[MAXN];
__device__ float g_att[MAXTOT];
__device__ int   g_cnt[MAXN];
__device__ int   g_off[MAXN + 1];
__device__ int   g_csrc[MAXTOT];
__device__ int   g_bsum[64];
__device__ int   g_total;
__device__ int   g_is64;

// ---------------- mma / ldmatrix helpers ----------------
__device__ __forceinline__ uint32_t smem_u32(const void* p) {
    uint32_t a;
    asm("{ .reg .u64 t; cvta.to.shared.u64 t, %1; cvt.u32.u64 %0, t; }" : "=r"(a) : "l"(p));
    return a;
}
__device__ __forceinline__ void ldsm4(uint32_t* r, uint32_t addr) {
    asm volatile("ldmatrix.sync.aligned.m8n8.x4.shared.b16 {%0,%1,%2,%3}, [%4];"
        : "=r"(r[0]), "=r"(r[1]), "=r"(r[2]), "=r"(r[3]) : "r"(addr));
}
__device__ __forceinline__ void mma16816(float* c, const uint32_t* a, const uint32_t* b) {
    asm volatile("mma.sync.aligned.m16n8k16.row.col.f32.bf16.bf16.f32 "
        "{%0,%1,%2,%3}, {%4,%5,%6,%7}, {%8,%9}, {%0,%1,%2,%3};"
        : "+f"(c[0]), "+f"(c[1]), "+f"(c[2]), "+f"(c[3])
        : "r"(a[0]), "r"(a[1]), "r"(a[2]), "r"(a[3]), "r"(b[0]), "r"(b[1]));
}

// ---------------- dtype detection ----------------
__global__ void detect_kernel(const int* __restrict__ ei) {
    if (threadIdx.x == 0 && blockIdx.x == 0) {
        int z = 1;
        #pragma unroll
        for (int i = 1; i < 64; i += 2)
            if (ei[i] != 0) z = 0;
        g_is64 = z;
    }
}
__device__ __forceinline__ int load_idx(const int* __restrict__ ei, long long elem, int is64) {
    return is64 ? ei[2 * elem] : ei[elem];
}

// ---------------- CSR build ----------------
__global__ void init_kernel(int n) {
    int i = blockIdx.x * blockDim.x + threadIdx.x;
    if (i < n) { g_cnt[i] = 1; g_asrc[i] = 0.f; g_adst[i] = 0.f; }
}
__global__ void zero_alpha_kernel(int n) {
    int i = blockIdx.x * blockDim.x + threadIdx.x;
    if (i < n) { g_asrc[i] = 0.f; g_adst[i] = 0.f; }
}
__global__ void hist_kernel(const int* __restrict__ ei, int E) {
    int i = blockIdx.x * blockDim.x + threadIdx.x;
    if (i >= E) return;
    int d = load_idx(ei, (long long)E + i, g_is64);
    atomicAdd(&g_cnt[d], 1);
}
__global__ __launch_bounds__(1024) void blockscan_kernel(int n) {
    __shared__ int warpsum[32];
    int i = blockIdx.x * 1024 + threadIdx.x;
    int v = (i < n) ? g_cnt[i] : 0;
    int lane = threadIdx.x & 31, wid = threadIdx.x >> 5;
    int s = v;
    #pragma unroll
    for (int o = 1; o < 32; o <<= 1) {
        int t = __shfl_up_sync(~0u, s, o);
        if (lane >= o) s += t;
    }
    if (lane == 31) warpsum[wid] = s;
    __syncthreads();
    if (wid == 0) {
        int ws = warpsum[lane];
        #pragma unroll
        for (int o = 1; o < 32; o <<= 1) {
            int t = __shfl_up_sync(~0u, ws, o);
            if (lane >= o) ws += t;
        }
        warpsum[lane] = ws;
    }
    __syncthreads();
    int excl = s - v + (wid ? warpsum[wid - 1] : 0);
    if (i < n) g_off[i] = excl;
    if (threadIdx.x == 1023) g_bsum[blockIdx.x] = excl + v;
}
__global__ void scanb_kernel(int nb) {
    if (threadIdx.x == 0 && blockIdx.x == 0) {
        int run = 0;
        for (int b = 0; b < nb; b++) { int t = g_bsum[b]; g_bsum[b] = run; run += t; }
        g_total = run;
    }
}
__global__ void finish_off_kernel(int n) {
    int i = blockIdx.x * 1024 + threadIdx.x;
    if (i < n) {
        int off = g_off[i] + g_bsum[i >> 10];
        g_off[i] = off;
        g_csrc[off] = i;
        g_cnt[i] = off + 1;
    }
    if (i == 0) g_off[n] = g_total;
}
__global__ void scatter_kernel(const int* __restrict__ ei, int E) {
    int i = blockIdx.x * blockDim.x + threadIdx.x;
    if (i >= E) return;
    int is64 = g_is64;
    int s = load_idx(ei, i, is64);
    int d = load_idx(ei, (long long)E + i, is64);
    int p = atomicAdd(&g_cnt[d], 1);
    g_csrc[p] = s;
}

// ---------------- W^T split: W[K][N] fp32 -> g_bth/g_btl [N][K] bf16 ----------
__global__ void wt_split_kernel(const float* __restrict__ W, int K, int N) {
    int i = blockIdx.x * blockDim.x + threadIdx.x;
    if (i >= N * K) return;
    int nn = i / K, kk = i - nn * K;
    float v = W[(size_t)kk * N + nn];
    __nv_bfloat16 h = __float2bfloat16(v);
    g_bth[i] = h;
    g_btl[i] = __float2bfloat16(v - __bfloat162float(h));
}

// ---- GEMM: block 128x128, 8 warps (2Mx4N), warp 64x32, mma.sync, hi/lo bf16 --
// C written as fp16 (gathered later); alpha from fp32 accumulators.
#define LDAB 48
#define OFF_AL 6144
#define OFF_BH 12288
#define OFF_BL 18432
#define STAGE_B 24576
#define SMEM_DYN (2 * STAGE_B)

__global__ __launch_bounds__(256, 2) void gemm_mma_kernel(
    const float* __restrict__ A, int Kfull,
    const __nv_bfloat16* __restrict__ Bth, const __nv_bfloat16* __restrict__ Btl,
    __half* __restrict__ C,
    const float* __restrict__ avs, const float* __restrict__ avd,
    int M, int N)
{
    extern __shared__ __align__(16) char buf[];
    uint32_t sb = smem_u32(buf);

    int tid = threadIdx.x;
    int w = tid >> 5, lane = tid & 31;
    int wr = w >> 2, wc = w & 3;                 // warp tile 64(M) x 32(N)
    int r0 = blockIdx.x * 128, c0 = blockIdx.y * 128;

    float acc[4][4][4];
    #pragma unroll
    for (int mt = 0; mt < 4; mt++)
        #pragma unroll
        for (int nt = 0; nt < 4; nt++)
            #pragma unroll
            for (int q = 0; q < 4; q++) acc[mt][nt][q] = 0.f;

    int s_row = tid >> 1, s_half = (tid & 1) * 8;

    // ldmatrix lane offsets — A pattern (m16k16)
    int la_row = (lane & 15), la_k = (lane >> 4) * 8;
    uint32_t a_frag_off = (uint32_t)(la_row * LDAB + la_k * 2);
    // B pattern (n16k16)
    int lb_n = (lane & 7) + ((lane >> 4) & 1) * 8;
    int lb_k = ((lane >> 3) & 1) * 8;
    uint32_t b_frag_off = (uint32_t)(lb_n * LDAB + lb_k * 2);

    float arv[8];
    uint4 bh_rv, bl_rv;
    int steps = Kfull / 16;

    {   // prologue: k-step 0
        int gr = r0 + s_row;
        float4 v0 = make_float4(0.f,0.f,0.f,0.f), v1 = v0;
        if (gr < M) {
            const float* ap = A + (size_t)gr * Kfull + s_half;
            v0 = *(const float4*)ap; v1 = *(const float4*)(ap + 4);
        }
        *(float4*)arv = v0; *(float4*)(arv + 4) = v1;
        size_t bo = (size_t)(c0 + s_row) * Kfull + s_half;
        bh_rv = *(const uint4*)(Bth + bo);
        bl_rv = *(const uint4*)(Btl + bo);
    }
    {   // store stage 0
        char* st = buf;
        __nv_bfloat16 hs[8], ls[8];
        #pragma unroll
        for (int q = 0; q < 8; q++) {
            hs[q] = __float2bfloat16(arv[q]);
            ls[q] = __float2bfloat16(arv[q] - __bfloat162float(hs[q]));
        }
        *(uint4*)(st + s_row * LDAB + s_half * 2)          = *(uint4*)hs;
        *(uint4*)(st + OFF_AL + s_row * LDAB + s_half * 2) = *(uint4*)ls;
        *(uint4*)(st + OFF_BH + s_row * LDAB + s_half * 2) = bh_rv;
        *(uint4*)(st + OFF_BL + s_row * LDAB + s_half * 2) = bl_rv;
    }
    __syncthreads();

    for (int i = 0; i < steps; i++) {
        int cur = i & 1, nxt = cur ^ 1;
        if (i + 1 < steps) {
            int k0 = (i + 1) * 16;
            int gr = r0 + s_row;
            float4 v0 = make_float4(0.f,0.f,0.f,0.f), v1 = v0;
            if (gr < M) {
                const float* ap = A + (size_t)gr * Kfull + k0 + s_half;
                v0 = *(const float4*)ap; v1 = *(const float4*)(ap + 4);
            }
            *(float4*)arv = v0; *(float4*)(arv + 4) = v1;
            size_t bo = (size_t)(c0 + s_row) * Kfull + k0 + s_half;
            bh_rv = *(const uint4*)(Bth + bo);
            bl_rv = *(const uint4*)(Btl + bo);
        }
        {
            uint32_t st = sb + cur * STAGE_B;
            uint32_t bh[2][4], bl[2][4];
            #pragma unroll
            for (int np = 0; np < 2; np++) {
                uint32_t nbase = st + OFF_BH + (uint32_t)((wc * 32 + np * 16) * LDAB) + b_frag_off;
                ldsm4(bh[np], nbase);
                ldsm4(bl[np], nbase + (OFF_BL - OFF_BH));
            }
            #pragma unroll
            for (int mt = 0; mt < 4; mt++) {
                uint32_t ah[4], al[4];
                uint32_t rbase = st + (uint32_t)((wr * 64 + mt * 16) * LDAB) + a_frag_off;
                ldsm4(ah, rbase);
                ldsm4(al, rbase + OFF_AL);
                #pragma unroll
                for (int nt = 0; nt < 4; nt++) {
                    const uint32_t* bhp = &bh[nt >> 1][(nt & 1) * 2];
                    const uint32_t* blp = &bl[nt >> 1][(nt & 1) * 2];
                    mma16816(acc[mt][nt], ah, bhp);
                    mma16816(acc[mt][nt], ah, blp);
                    mma16816(acc[mt][nt], al, bhp);
                }
            }
        }
        if (i + 1 < steps) {
            char* st = buf + nxt * STAGE_B;
            __nv_bfloat16 hs[8], ls[8];
            #pragma unroll
            for (int q = 0; q < 8; q++) {
                hs[q] = __float2bfloat16(arv[q]);
                ls[q] = __float2bfloat16(arv[q] - __bfloat162float(hs[q]));
            }
            *(uint4*)(st + s_row * LDAB + s_half * 2)          = *(uint4*)hs;
            *(uint4*)(st + OFF_AL + s_row * LDAB + s_half * 2) = *(uint4*)ls;
            *(uint4*)(st + OFF_BH + s_row * LDAB + s_half * 2) = bh_rv;
            *(uint4*)(st + OFF_BL + s_row * LDAB + s_half * 2) = bl_rv;
        }
        __syncthreads();
    }

    // ---- store C (fp16) + fused alpha partials from fp32 accumulators ----
    {
        float as[4][2], ad[4][2];
        #pragma unroll
        for (int nt = 0; nt < 4; nt++) {
            int col = c0 + wc * 32 + nt * 8 + (lane & 3) * 2;
            as[nt][0] = avs[col];     as[nt][1] = avs[col + 1];
            ad[nt][0] = avd[col];     ad[nt][1] = avd[col + 1];
        }
        #pragma unroll
        for (int mt = 0; mt < 4; mt++) {
            int rA = r0 + wr * 64 + mt * 16 + (lane >> 2);
            int rB = rA + 8;
            float ssA = 0.f, sdA = 0.f, ssB = 0.f, sdB = 0.f;
            #pragma unroll
            for (int nt = 0; nt < 4; nt++) {
                float* c = acc[mt][nt];
                int col = c0 + wc * 32 + nt * 8 + (lane & 3) * 2;
                *(__half2*)(C + (size_t)rA * N + col) = __floats2half2_rn(c[0], c[1]);
                *(__half2*)(C + (size_t)rB * N + col) = __floats2half2_rn(c[2], c[3]);
                ssA += c[0] * as[nt][0] + c[1] * as[nt][1];
                sdA += c[0] * ad[nt][0] + c[1] * ad[nt][1];
                ssB += c[2] * as[nt][0] + c[3] * as[nt][1];
                sdB += c[2] * ad[nt][0] + c[3] * ad[nt][1];
            }
            #pragma unroll
            for (int o = 1; o < 4; o <<= 1) {
                ssA += __shfl_xor_sync(~0u, ssA, o);
                sdA += __shfl_xor_sync(~0u, sdA, o);
                ssB += __shfl_xor_sync(~0u, ssB, o);
                sdB += __shfl_xor_sync(~0u, sdB, o);
            }
            if ((lane & 3) == 0) {
                if (rA < M) { atomicAdd(&g_asrc[rA], ssA); atomicAdd(&g_adst[rA], sdA); }
                if (rB < M) { atomicAdd(&g_asrc[rB], ssB); atomicAdd(&g_adst[rB], sdB); }
            }
        }
    }
}

// ---------------- segment softmax: stats + normalized att per edge ----------
__global__ void stats_kernel(int n) {
    int w = (blockIdx.x * blockDim.x + threadIdx.x) >> 5;
    int lane = threadIdx.x & 31;
    if (w >= n) return;
    int beg = g_off[w], end = g_off[w + 1];
    float adi = g_adst[w];
    float mx = -1e30f, sm = 0.f;
    for (int k = beg + lane; k < end; k += 32) {
        int s = g_csrc[k];
        float e = g_asrc[s] + adi;
        e = e >= 0.f ? e : 0.2f * e;
        if (e > mx) { sm = sm * __expf(mx - e) + 1.f; mx = e; }
        else        { sm += __expf(e - mx); }
    }
    #pragma unroll
    for (int o = 16; o; o >>= 1) {
        float mo = __shfl_xor_sync(~0u, mx, o);
        float so = __shfl_xor_sync(~0u, sm, o);
        float nm = fmaxf(mx, mo);
        sm = sm * __expf(mx - nm) + so * __expf(mo - nm);
        mx = nm;
    }
    float inv = 1.f / sm;
    for (int k = beg + lane; k < end; k += 32) {
        int s = g_csrc[k];
        float e = g_asrc[s] + adi;
        e = e >= 0.f ? e : 0.2f * e;
        g_att[k] = __expf(e - mx) * inv;
    }
}

// ------- aggregation (warp per node, fp16 row gather, fp32 accumulate) -------
template<int F, bool RELU>
__global__ void agg_kernel(const __half* __restrict__ xw,
                           const float* __restrict__ bias,
                           float* __restrict__ out, int n)
{
    int w = (blockIdx.x * blockDim.x + threadIdx.x) >> 5;
    int lane = threadIdx.x & 31;
    if (w >= n) return;
    const int NV = F / 32;                      // halves per lane (8 or 4)
    int beg = g_off[w], end = g_off[w + 1];
    float acc[NV];
    #pragma unroll
    for (int q = 0; q < NV; q++) acc[q] = 0.f;

    int k = beg;
    for (; k + 2 <= end; k += 2) {
        int s0 = g_csrc[k], s1 = g_csrc[k + 1];
        float a0 = g_att[k], a1 = g_att[k + 1];
        const __half* r0p = xw + (size_t)s0 * F + lane * NV;
        const __half* r1p = xw + (size_t)s1 * F + lane * NV;
        if (NV == 8) {
            uint4 u0 = *(const uint4*)r0p;
            uint4 u1 = *(const uint4*)r1p;
            const __half2* h0 = (const __half2*)&u0;
            const __half2* h1 = (const __half2*)&u1;
            #pragma unroll
            for (int q = 0; q < 4; q++) {
                float2 f0 = __half22float2(h0[q]);
                float2 f1 = __half22float2(h1[q]);
                acc[2*q]   += a0 * f0.x + a1 * f1.x;
                acc[2*q+1] += a0 * f0.y + a1 * f1.y;
            }
        } else {
            uint2 u0 = *(const uint2*)r0p;
            uint2 u1 = *(const uint2*)r1p;
            const __half2* h0 = (const __half2*)&u0;
            const __half2* h1 = (const __half2*)&u1;
            #pragma unroll
            for (int q = 0; q < 2; q++) {
                float2 f0 = __half22float2(h0[q]);
                float2 f1 = __half22float2(h1[q]);
                acc[2*q]   += a0 * f0.x + a1 * f1.x;
                acc[2*q+1] += a0 * f0.y + a1 * f1.y;
            }
        }
    }
    if (k < end) {
        int s0 = g_csrc[k];
        float a0 = g_att[k];
        const __half* r0p = xw + (size_t)s0 * F + lane * NV;
        if (NV == 8) {
            uint4 u0 = *(const uint4*)r0p;
            const __half2* h0 = (const __half2*)&u0;
            #pragma unroll
            for (int q = 0; q < 4; q++) {
                float2 f0 = __half22float2(h0[q]);
                acc[2*q]   += a0 * f0.x;
                acc[2*q+1] += a0 * f0.y;
            }
        } else {
            uint2 u0 = *(const uint2*)r0p;
            const __half2* h0 = (const __half2*)&u0;
            #pragma unroll
            for (int q = 0; q < 2; q++) {
                float2 f0 = __half22float2(h0[q]);
                acc[2*q]   += a0 * f0.x;
                acc[2*q+1] += a0 * f0.y;
            }
        }
    }
    // bias + (relu) + store fp32
    const float* bp = bias + lane * NV;
    float* op = out + (size_t)w * F + lane * NV;
    #pragma unroll
    for (int q = 0; q < NV; q += 4) {
        float4 b4 = *(const float4*)(bp + q);
        float4 o4 = make_float4(acc[q] + b4.x, acc[q+1] + b4.y,
                                acc[q+2] + b4.z, acc[q+3] + b4.w);
        if (RELU) {
            o4.x = fmaxf(o4.x, 0.f); o4.y = fmaxf(o4.y, 0.f);
            o4.z = fmaxf(o4.z, 0.f); o4.w = fmaxf(o4.w, 0.f);
        }
        *(float4*)(op + q) = o4;
    }
}

// ---------------- launch ----------------
extern "C" void kernel_launch(void* const* d_in, const int* in_sizes, int n_in,
                              void* d_out, int out_size) {
    const float* x   = (const float*)d_in[0];
    const int*   ei  = (const int*)d_in[1];
    const float* W1  = (const float*)d_in[2];
    const float* a1s = (const float*)d_in[3];
    const float* a1d = (const float*)d_in[4];
    const float* b1  = (const float*)d_in[5];
    const float* W2  = (const float*)d_in[6];
    const float* a2s = (const float*)d_in[7];
    const float* a2d = (const float*)d_in[8];
    const float* b2  = (const float*)d_in[9];
    float* out = (float*)d_out;

    int n = in_sizes[0] / 128;        // 50000
    int E = in_sizes[1] / 2;          // 800000

    __half* p_xwh = nullptr;
    float*  p_h   = nullptr;
    __nv_bfloat16 *p_bth = nullptr, *p_btl = nullptr;
    cudaGetSymbolAddress((void**)&p_xwh, g_xwh);
    cudaGetSymbolAddress((void**)&p_h,   g_h);
    cudaGetSymbolAddress((void**)&p_bth, g_bth);
    cudaGetSymbolAddress((void**)&p_btl, g_btl);

    cudaFuncSetAttribute(gemm_mma_kernel, cudaFuncAttributeMaxDynamicSharedMemorySize, SMEM_DYN);

    int nblk    = (n + 255) / 256;
    int eblk    = (E + 255) / 256;
    int warpBlk = (n * 32 + 255) / 256;
    int sblk    = (n + 1023) / 1024;
    int rtiles  = (n + 127) / 128;    // 391
    dim3 g1(rtiles, 2);               // layer1: N=256 -> 2 col tiles of 128
    dim3 g2(rtiles, 1);               // layer2: N=128 -> 1 col tile

    // gemm1 lands in ncu's profiled slot (4th launch)
    detect_kernel<<<1, 32>>>(ei);
    init_kernel<<<nblk, 256>>>(n);
    wt_split_kernel<<<(128 * 256 + 255) / 256, 256>>>(W1, 128, 256);
    gemm_mma_kernel<<<g1, 256, SMEM_DYN>>>(x, 128, p_bth, p_btl, p_xwh, a1s, a1d, n, 256);
    hist_kernel<<<eblk, 256>>>(ei, E);
    blockscan_kernel<<<sblk, 1024>>>(n);
    scanb_kernel<<<1, 32>>>(sblk);
    finish_off_kernel<<<sblk, 1024>>>(n);
    scatter_kernel<<<eblk, 256>>>(ei, E);

    // ---- layer 1 tail ----
    stats_kernel<<<warpBlk, 256>>>(n);
    zero_alpha_kernel<<<nblk, 256>>>(n);
    agg_kernel<256, true><<<warpBlk, 256>>>(p_xwh, b1, p_h, n);

    // ---- layer 2 ----
    wt_split_kernel<<<(256 * 128 + 255) / 256, 256>>>(W2, 256, 128);
    gemm_mma_kernel<<<g2, 256, SMEM_DYN>>>(p_h, 256, p_bth, p_btl, p_xwh, a2s, a2d, n, 128);
    stats_kernel<<<warpBlk, 256>>>(n);
    agg_kernel<128, false><<<warpBlk, 256>>>(p_xwh, b2, out, n);
}